// round 8
// baseline (speedup 1.0000x reference)
#include <cuda_runtime.h>
#include <cuda_bf16.h>
#include <cstdint>
#include <cstddef>
#include <math.h>

// Problem constants
#define Dm   2048
#define Hh   32
#define DSs  64
#define KK   4
#define EPSf 1e-6f
#define NC   32            // scan chunks

// Max sizes (B=2, L=4096)
#define BL_MAX  8192
#define P_COLS  (3*Dm)   // 6144
#define NB_MAX  64       // B*H chains

// Scratch layout (floats)
#define OFF_XN     ((size_t)0)
#define OFF_XC     ((size_t)BL_MAX*Dm)
#define OFF_P      (OFF_XC + (size_t)BL_MAX*Dm)
#define OFF_GATE   (OFF_P  + (size_t)BL_MAX*P_COLS)
#define OFF_MIXED  (OFF_GATE + (size_t)BL_MAX*Dm)
#define OFF_SCANA  (OFF_MIXED + (size_t)BL_MAX*Dm)
#define OFF_SCANH  (OFF_SCANA + (size_t)NB_MAX*NC*DSs)
#define OFF_SCANI  (OFF_SCANH + (size_t)NB_MAX*NC*DSs)
#define OFF_PPR    (OFF_SCANI + (size_t)NB_MAX*NC*DSs)
#define OFF_GPR    (OFF_PPR + (size_t)P_COLS*Dm)
#define OFF_OPR    (OFF_GPR + (size_t)Dm*Dm)
#define SCRATCH_FLOATS (OFF_OPR + (size_t)Dm*Dm)

__device__ float g_scratch[SCRATCH_FLOATS];

// ---------------------------------------------------------------------------
// Helpers
// ---------------------------------------------------------------------------
__device__ __forceinline__ float rn_tf32(float v) {
    uint32_t u;
    asm("cvt.rna.tf32.f32 %0, %1;" : "=r"(u) : "f"(v));
    return __uint_as_float(u);
}

__device__ __forceinline__ void mma_tf32(float* c, const uint32_t* a, const uint32_t* b) {
    asm volatile(
        "mma.sync.aligned.m16n8k8.row.col.f32.tf32.tf32.f32 "
        "{%0,%1,%2,%3}, {%4,%5,%6,%7}, {%8,%9}, {%0,%1,%2,%3};\n"
        : "+f"(c[0]), "+f"(c[1]), "+f"(c[2]), "+f"(c[3])
        : "r"(a[0]), "r"(a[1]), "r"(a[2]), "r"(a[3]),
          "r"(b[0]), "r"(b[1]));
}

__device__ __forceinline__ void cp_async16(void* smem, const void* gmem) {
    uint32_t s = (uint32_t)__cvta_generic_to_shared(smem);
    asm volatile("cp.async.cg.shared.global [%0], [%1], 16;\n" :: "r"(s), "l"(gmem));
}

__device__ __forceinline__ float sigmoidf_(float v) {
    return 1.0f / (1.0f + __expf(-v));
}

// ---------------------------------------------------------------------------
// Weight tf32 round (grid-stride float4 copy)
// ---------------------------------------------------------------------------
__global__ void round_weights(const float* __restrict__ W, float* __restrict__ R,
                              int n4) {
    int i = blockIdx.x * blockDim.x + threadIdx.x;
    int stride = gridDim.x * blockDim.x;
    const float4* w4 = (const float4*)W;
    float4* r4 = (float4*)R;
    for (; i < n4; i += stride) {
        float4 v = w4[i];
        v.x = rn_tf32(v.x); v.y = rn_tf32(v.y);
        v.z = rn_tf32(v.z); v.w = rn_tf32(v.w);
        r4[i] = v;
    }
}

// ---------------------------------------------------------------------------
// RMSNorm (stores tf32-rounded xn)
// ---------------------------------------------------------------------------
__global__ void rmsnorm_kernel(const float* __restrict__ x,
                               const float* __restrict__ w,
                               float* __restrict__ xn) {
    size_t row = blockIdx.x;
    const float4* xr = (const float4*)(x + row * Dm);
    float4 v0 = xr[threadIdx.x];
    float4 v1 = xr[threadIdx.x + 256];
    float ss = v0.x*v0.x + v0.y*v0.y + v0.z*v0.z + v0.w*v0.w
             + v1.x*v1.x + v1.y*v1.y + v1.z*v1.z + v1.w*v1.w;
    #pragma unroll
    for (int o = 16; o > 0; o >>= 1) ss += __shfl_xor_sync(0xffffffffu, ss, o);
    __shared__ float red[8];
    if ((threadIdx.x & 31) == 0) red[threadIdx.x >> 5] = ss;
    __syncthreads();
    float tot = red[0] + red[1] + red[2] + red[3] + red[4] + red[5] + red[6] + red[7];
    float inv = rsqrtf(tot * (1.0f / Dm) + EPSf);

    const float4* wr = (const float4*)w;
    float4 w0 = wr[threadIdx.x];
    float4 w1 = wr[threadIdx.x + 256];
    float4 o0, o1;
    o0.x = rn_tf32(v0.x * w0.x * inv); o0.y = rn_tf32(v0.y * w0.y * inv);
    o0.z = rn_tf32(v0.z * w0.z * inv); o0.w = rn_tf32(v0.w * w0.w * inv);
    o1.x = rn_tf32(v1.x * w1.x * inv); o1.y = rn_tf32(v1.y * w1.y * inv);
    o1.z = rn_tf32(v1.z * w1.z * inv); o1.w = rn_tf32(v1.w * w1.w * inv);
    float4* orow = (float4*)(xn + row * Dm);
    orow[threadIdx.x]       = o0;
    orow[threadIdx.x + 256] = o1;
}

// ---------------------------------------------------------------------------
// Causal depthwise conv (K=4) + SiLU (stores tf32-rounded xc)
// ---------------------------------------------------------------------------
__global__ void conv_silu_kernel(const float* __restrict__ xn,
                                 const float* __restrict__ cw,
                                 const float* __restrict__ cb,
                                 float* __restrict__ xc, int L) {
    int d  = blockIdx.x * 128 + threadIdx.x;
    int b  = blockIdx.z;
    int l0 = blockIdx.y * 256;
    float w0 = cw[d*KK + 0], w1 = cw[d*KK + 1], w2 = cw[d*KK + 2], w3 = cw[d*KK + 3];
    float bb = cb[d];
    const float* base = xn + ((size_t)b * L) * Dm + d;
    float* obase      = xc + ((size_t)b * L) * Dm + d;

    float xm3 = (l0 >= 3) ? base[(size_t)(l0 - 3) * Dm] : 0.0f;
    float xm2 = (l0 >= 2) ? base[(size_t)(l0 - 2) * Dm] : 0.0f;
    float xm1 = (l0 >= 1) ? base[(size_t)(l0 - 1) * Dm] : 0.0f;

    #pragma unroll 8
    for (int l = l0; l < l0 + 256; l++) {
        float xcur = base[(size_t)l * Dm];
        float acc = bb + w0 * xm3 + w1 * xm2 + w2 * xm1 + w3 * xcur;
        float sv = acc * sigmoidf_(acc);
        obase[(size_t)l * Dm] = rn_tf32(sv);
        xm3 = xm2; xm2 = xm1; xm1 = xcur;
    }
}

// ---------------------------------------------------------------------------
// TF32 GEMM, BK=32, 3-stage cp.async pipeline, ONE __syncthreads per K-tile.
// Inputs PRE-ROUNDED to tf32 in memory -> fragments loaded as raw u32.
//   MODE 0: +bias   MODE 1: sigmoid(+bias)   MODE 2: +bias+res
// Tiles: BM=128, BN=128, BK=32, 256 threads (8 warps of 64x32), 2 CTAs/SM.
// ---------------------------------------------------------------------------
#define GBM 128
#define GBN 128
#define GBK 32
#define NST 3
#define SA_STR 36    // 36 mod 32 = 4 -> conflict-free A fragment loads
#define SB_STR 136   // 136 mod 32 = 8 -> conflict-free B fragment loads
#define SA_ELEMS (GBM * SA_STR)   // 4608
#define SB_ELEMS (GBK * SB_STR)   // 4352
#define STG_ELEMS (SA_ELEMS + SB_ELEMS)          // 8960 floats = 35840 B
#define GEMM_SMEM_BYTES (NST * STG_ELEMS * 4)    // 107520 B

template<int MODE>
__global__ __launch_bounds__(256, 2)
void gemm_tf32(const float* __restrict__ A, const float* __restrict__ Bw,
               const float* __restrict__ bias, const float* __restrict__ res,
               float* __restrict__ C, int M, int N, int K) {
    extern __shared__ float smem[];

    int tid  = threadIdx.x;
    int wid  = tid >> 5;
    int lane = tid & 31;
    int wm = (wid & 1) * 64;
    int wn = (wid >> 1) * 32;
    int g = lane >> 2;
    int t = lane & 3;

    int bm = blockIdx.y * GBM;
    int bn = blockIdx.x * GBN;

    const float* Aptr = A + (size_t)bm * K;
    const float* Bptr = Bw + bn;

    float acc[4][4][4];
    #pragma unroll
    for (int i = 0; i < 4; i++)
        #pragma unroll
        for (int j = 0; j < 4; j++)
            #pragma unroll
            for (int q = 0; q < 4; q++) acc[i][j][q] = 0.0f;

    int a_r0 = tid >> 3;            // 0..31
    int a_c0 = (tid & 7) * 4;       // 0..28
    int b_r0 = tid >> 5;            // 0..7
    int b_c0 = (tid & 31) * 4;

    int NK = K / GBK;

    // Prologue: stages 0 and 1 (NST-1 groups in flight)
    #pragma unroll
    for (int s = 0; s < NST - 1; s++) {
        float* stA = smem + s * STG_ELEMS;
        float* stB = stA + SA_ELEMS;
        int k0 = s * GBK;
        #pragma unroll
        for (int i = 0; i < 4; i++) {
            int r = a_r0 + 32 * i;
            cp_async16(&stA[r * SA_STR + a_c0], Aptr + (size_t)r * K + k0 + a_c0);
        }
        #pragma unroll
        for (int i = 0; i < 4; i++) {
            int r = b_r0 + 8 * i;
            cp_async16(&stB[r * SB_STR + b_c0], Bptr + (size_t)(k0 + r) * N + b_c0);
        }
        asm volatile("cp.async.commit_group;\n" ::);
    }

    int rd = 0;                         // read stage
    int wr = NST - 1;                   // write stage
    for (int kt = 0; kt < NK; kt++) {
        if (kt < NK - 1) asm volatile("cp.async.wait_group %0;\n" :: "n"(NST - 2));
        else             asm volatile("cp.async.wait_group 0;\n" ::);
        __syncthreads();

        const uint32_t* cA = (const uint32_t*)(smem + rd * STG_ELEMS);
        const uint32_t* cB = cA + SA_ELEMS;

        bool has_next = (kt + NST - 1) < NK;
        float* nA = smem + wr * STG_ELEMS;
        float* nB = nA + SA_ELEMS;
        int k0n = (kt + NST - 1) * GBK;

        #pragma unroll
        for (int k8 = 0; k8 < 4; k8++) {
            uint32_t af[4][4], bf[4][2];
            #pragma unroll
            for (int mt = 0; mt < 4; mt++) {
                int r = wm + mt * 16 + g;
                int c = k8 * 8 + t;
                af[mt][0] = cA[r * SA_STR + c];
                af[mt][1] = cA[(r + 8) * SA_STR + c];
                af[mt][2] = cA[r * SA_STR + c + 4];
                af[mt][3] = cA[(r + 8) * SA_STR + c + 4];
            }
            #pragma unroll
            for (int nt = 0; nt < 4; nt++) {
                int n = wn + nt * 8 + g;
                int k = k8 * 8 + t;
                bf[nt][0] = cB[k * SB_STR + n];
                bf[nt][1] = cB[(k + 4) * SB_STR + n];
            }
            // Interleave next-tile loads: 2 cp.async per k8 step
            if (has_next) {
                #pragma unroll
                for (int j = 0; j < 2; j++) {
                    int i = k8 * 2 + j;
                    if (i < 4) {
                        int r = a_r0 + 32 * i;
                        cp_async16(&nA[r * SA_STR + a_c0],
                                   Aptr + (size_t)r * K + k0n + a_c0);
                    } else {
                        int r = b_r0 + 8 * (i - 4);
                        cp_async16(&nB[r * SB_STR + b_c0],
                                   Bptr + (size_t)(k0n + r) * N + b_c0);
                    }
                }
            }
            #pragma unroll
            for (int mt = 0; mt < 4; mt++)
                #pragma unroll
                for (int nt = 0; nt < 4; nt++)
                    mma_tf32(acc[mt][nt], af[mt], bf[nt]);
        }
        if (has_next) asm volatile("cp.async.commit_group;\n" ::);

        rd = (rd + 1) % NST;
        wr = (wr + 1) % NST;
    }

    // Epilogue
    #pragma unroll
    for (int mt = 0; mt < 4; mt++) {
        #pragma unroll
        for (int nt = 0; nt < 4; nt++) {
            int r = bm + wm + mt * 16 + g;
            int c = bn + wn + nt * 8 + 2 * t;
            float b0 = bias[c], b1 = bias[c + 1];
            float v00 = acc[mt][nt][0] + b0;
            float v01 = acc[mt][nt][1] + b1;
            float v10 = acc[mt][nt][2] + b0;
            float v11 = acc[mt][nt][3] + b1;
            if (MODE == 1) {
                v00 = sigmoidf_(v00); v01 = sigmoidf_(v01);
                v10 = sigmoidf_(v10); v11 = sigmoidf_(v11);
            }
            if (MODE == 2) {
                float2 r0 = *(const float2*)&res[(size_t)r * N + c];
                float2 r1 = *(const float2*)&res[(size_t)(r + 8) * N + c];
                v00 += r0.x; v01 += r0.y; v10 += r1.x; v11 += r1.y;
            }
            *(float2*)&C[(size_t)r * N + c]       = make_float2(v00, v01);
            *(float2*)&C[(size_t)(r + 8) * N + c] = make_float2(v10, v11);
        }
    }
}

// ---------------------------------------------------------------------------
// Chunked parallel scan (3 passes). scan_p3 stores tf32-rounded mixed.
// ---------------------------------------------------------------------------
__global__ void scan_p1(const float* __restrict__ p,
                        float* __restrict__ Ac, float* __restrict__ Hc,
                        int L, int CL) {
    int chain = blockIdx.x;
    int chunk = blockIdx.y;
    int b = chain / Hh;
    int h = chain % Hh;
    int s = threadIdx.x;

    const size_t pstr = (size_t)Hh * 3 * DSs;
    const float* pb = p + ((size_t)b * L + (size_t)chunk * CL) * pstr
                        + (size_t)h * 3 * DSs + s;

    float A = 1.0f, hl = 0.0f;
    for (int l = 0; l < CL; l += 4) {
        float d0 = __ldg(pb + (size_t)(l+0) * pstr);
        float d1 = __ldg(pb + (size_t)(l+1) * pstr);
        float d2 = __ldg(pb + (size_t)(l+2) * pstr);
        float d3 = __ldg(pb + (size_t)(l+3) * pstr);
        float b0 = __ldg(pb + (size_t)(l+0) * pstr + DSs);
        float b1 = __ldg(pb + (size_t)(l+1) * pstr + DSs);
        float b2 = __ldg(pb + (size_t)(l+2) * pstr + DSs);
        float b3 = __ldg(pb + (size_t)(l+3) * pstr + DSs);
        float s0 = sigmoidf_(d0), s1 = sigmoidf_(d1);
        float s2 = sigmoidf_(d2), s3 = sigmoidf_(d3);
        A *= s0; hl = fmaf(s0, hl, b0);
        A *= s1; hl = fmaf(s1, hl, b1);
        A *= s2; hl = fmaf(s2, hl, b2);
        A *= s3; hl = fmaf(s3, hl, b3);
    }
    size_t idx = ((size_t)chain * NC + chunk) * DSs + s;
    Ac[idx] = A;
    Hc[idx] = hl;
}

__global__ void scan_mid(const float* __restrict__ Ac, const float* __restrict__ Hc,
                         const float* __restrict__ st0,
                         float* __restrict__ hin, float* __restrict__ hlast) {
    int chain = blockIdx.x;
    int s = threadIdx.x;
    float h = st0[(size_t)chain * DSs + s];
    #pragma unroll
    for (int c = 0; c < NC; c++) {
        size_t idx = ((size_t)chain * NC + c) * DSs + s;
        hin[idx] = h;
        h = fmaf(Ac[idx], h, Hc[idx]);
    }
    hlast[(size_t)chain * DSs + s] = h;
}

__global__ void scan_p3(const float* __restrict__ p,
                        const float* __restrict__ gate,
                        const float* __restrict__ xn,
                        const float* __restrict__ hin,
                        float* __restrict__ mixed, int L, int CL) {
    int chain = blockIdx.x;
    int chunk = blockIdx.y;
    int b = chain / Hh;
    int h = chain % Hh;
    int s = threadIdx.x;

    float hst = hin[((size_t)chain * NC + chunk) * DSs + s];

    const size_t pstr = (size_t)Hh * 3 * DSs;
    size_t l0 = (size_t)chunk * CL;
    const float* pb = p + ((size_t)b * L + l0) * pstr + (size_t)h * 3 * DSs + s;
    size_t goff = ((size_t)b * L + l0) * Dm + (size_t)h * DSs + s;
    const float* gb = gate + goff;
    const float* xb = xn + goff;
    float* mb = mixed + goff;

    for (int l = 0; l < CL; l += 4) {
        float dv[4], bv[4], cv[4], gv[4], xv[4];
        #pragma unroll
        for (int u = 0; u < 4; u++) {
            const float* pp = pb + (size_t)(l + u) * pstr;
            dv[u] = __ldg(pp);
            bv[u] = __ldg(pp + DSs);
            cv[u] = __ldg(pp + 2 * DSs);
            gv[u] = __ldg(gb + (size_t)(l + u) * Dm);
            xv[u] = __ldg(xb + (size_t)(l + u) * Dm);
        }
        #pragma unroll
        for (int u = 0; u < 4; u++) {
            float dsg = sigmoidf_(dv[u]);
            hst = fmaf(dsg, hst, bv[u]);
            float ssm = cv[u] * hst;
            mb[(size_t)(l + u) * Dm] = rn_tf32(fmaf(gv[u], ssm - xv[u], xv[u]));
        }
    }
}

// ---------------------------------------------------------------------------
// Launch
// ---------------------------------------------------------------------------
extern "C" void kernel_launch(void* const* d_in, const int* in_sizes, int n_in,
                              void* d_out, int out_size) {
    const float* x      = (const float*)d_in[0];
    const float* state  = (const float*)d_in[1];
    const float* norm_w = (const float*)d_in[2];
    const float* conv_w = (const float*)d_in[3];
    const float* conv_b = (const float*)d_in[4];
    const float* pp_w   = (const float*)d_in[5];
    const float* pp_b   = (const float*)d_in[6];
    const float* gp_w   = (const float*)d_in[7];
    const float* gp_b   = (const float*)d_in[8];
    const float* op_w   = (const float*)d_in[9];
    const float* op_b   = (const float*)d_in[10];
    float* out = (float*)d_out;

    int BL = in_sizes[0] / Dm;                 // 8192
    int Bb = in_sizes[1] / (Hh * DSs);         // 2
    int L  = BL / Bb;                          // 4096
    int NBc = Bb * Hh;                         // 64
    int CL  = L / NC;                          // 128

    static bool attr_done = false;
    if (!attr_done) {
        cudaFuncSetAttribute(gemm_tf32<0>, cudaFuncAttributeMaxDynamicSharedMemorySize, GEMM_SMEM_BYTES);
        cudaFuncSetAttribute(gemm_tf32<1>, cudaFuncAttributeMaxDynamicSharedMemorySize, GEMM_SMEM_BYTES);
        cudaFuncSetAttribute(gemm_tf32<2>, cudaFuncAttributeMaxDynamicSharedMemorySize, GEMM_SMEM_BYTES);
        attr_done = true;
    }

    float* scratch;
    cudaGetSymbolAddress((void**)&scratch, g_scratch);
    float* xn    = scratch + OFF_XN;
    float* xc    = scratch + OFF_XC;
    float* p     = scratch + OFF_P;
    float* gatep = scratch + OFF_GATE;
    float* mixed = scratch + OFF_MIXED;
    float* scanA = scratch + OFF_SCANA;
    float* scanH = scratch + OFF_SCANH;
    float* scanI = scratch + OFF_SCANI;
    float* ppR   = scratch + OFF_PPR;
    float* gpR   = scratch + OFF_GPR;
    float* opR   = scratch + OFF_OPR;

    // 0) Weight tf32 rounding (removes cvt from GEMM inner loops)
    round_weights<<<1184, 256>>>(pp_w, ppR, (Dm * P_COLS) / 4);
    round_weights<<<1184, 256>>>(gp_w, gpR, (Dm * Dm) / 4);
    round_weights<<<1184, 256>>>(op_w, opR, (Dm * Dm) / 4);

    // 1) RMSNorm (tf32-rounded xn)
    rmsnorm_kernel<<<BL, 256>>>(x, norm_w, xn);

    // 2) Causal conv + SiLU (tf32-rounded xc)
    conv_silu_kernel<<<dim3(Dm / 128, L / 256, Bb), 128>>>(xn, conv_w, conv_b, xc, L);

    // 3) p = xn @ pp_w + pp_b
    gemm_tf32<0><<<dim3(P_COLS / GBN, BL / GBM), 256, GEMM_SMEM_BYTES>>>(
        xn, ppR, pp_b, nullptr, p, BL, P_COLS, Dm);

    // 4) gate = sigmoid(xc @ gp_w + gp_b)
    gemm_tf32<1><<<dim3(Dm / GBN, BL / GBM), 256, GEMM_SMEM_BYTES>>>(
        xc, gpR, gp_b, nullptr, gatep, BL, Dm, Dm);

    // 5) scan (3 passes); h_last to tail of output
    scan_p1<<<dim3(NBc, NC), DSs>>>(p, scanA, scanH, L, CL);
    scan_mid<<<NBc, DSs>>>(scanA, scanH, state, scanI, out + (size_t)BL * Dm);
    scan_p3<<<dim3(NBc, NC), DSs>>>(p, gatep, xn, scanI, mixed, L, CL);

    // 6) y = mixed @ op_w + op_b + x
    gemm_tf32<2><<<dim3(Dm / GBN, BL / GBM), 256, GEMM_SMEM_BYTES>>>(
        mixed, opR, op_b, x, out, BL, Dm, Dm);
}

// round 9
// speedup vs baseline: 1.3917x; 1.3917x over previous
#include <cuda_runtime.h>
#include <cuda_fp16.h>
#include <cstdint>
#include <cstddef>
#include <math.h>

// Problem constants
#define Dm   2048
#define Hh   32
#define DSs  64
#define KK   4
#define EPSf 1e-6f
#define NC   32            // scan chunks

// Max sizes (B=2, L=4096)
#define BL_MAX  8192
#define P_COLS  (3*Dm)   // 6144
#define NB_MAX  64       // B*H chains

// Scratch layout (floats)
#define OFF_XNH    ((size_t)0)                               // half[BL*Dm]
#define OFF_XCH    (OFF_XNH + (size_t)BL_MAX*Dm/2)
#define OFF_MXH    (OFF_XCH + (size_t)BL_MAX*Dm/2)
#define OFF_P      (OFF_MXH + (size_t)BL_MAX*Dm/2)
#define OFF_GATE   (OFF_P   + (size_t)BL_MAX*P_COLS)
#define OFF_SCANA  (OFF_GATE + (size_t)BL_MAX*Dm)
#define OFF_SCANH  (OFF_SCANA + (size_t)NB_MAX*NC*DSs)
#define OFF_SCANI  (OFF_SCANH + (size_t)NB_MAX*NC*DSs)
#define OFF_PPH    (OFF_SCANI + (size_t)NB_MAX*NC*DSs)       // half[P_COLS*Dm]
#define OFF_GPH    (OFF_PPH + (size_t)P_COLS*Dm/2)
#define OFF_OPH    (OFF_GPH + (size_t)Dm*Dm/2)
#define SCRATCH_FLOATS (OFF_OPH + (size_t)Dm*Dm/2)

__device__ float g_scratch[SCRATCH_FLOATS];

// ---------------------------------------------------------------------------
// Helpers
// ---------------------------------------------------------------------------
__device__ __forceinline__ void mma_f16(float* c, const uint32_t* a, const uint32_t* b) {
    asm volatile(
        "mma.sync.aligned.m16n8k16.row.col.f32.f16.f16.f32 "
        "{%0,%1,%2,%3}, {%4,%5,%6,%7}, {%8,%9}, {%0,%1,%2,%3};\n"
        : "+f"(c[0]), "+f"(c[1]), "+f"(c[2]), "+f"(c[3])
        : "r"(a[0]), "r"(a[1]), "r"(a[2]), "r"(a[3]),
          "r"(b[0]), "r"(b[1]));
}

__device__ __forceinline__ void cp_async16(void* smem, const void* gmem) {
    uint32_t s = (uint32_t)__cvta_generic_to_shared(smem);
    asm volatile("cp.async.cg.shared.global [%0], [%1], 16;\n" :: "r"(s), "l"(gmem));
}

__device__ __forceinline__ float sigmoidf_(float v) {
    return 1.0f / (1.0f + __expf(-v));
}

__device__ __forceinline__ uint2 pack4h(float a, float b, float c, float d) {
    __half2 lo = __floats2half2_rn(a, b);
    __half2 hi = __floats2half2_rn(c, d);
    uint2 r;
    r.x = *(uint32_t*)&lo;
    r.y = *(uint32_t*)&hi;
    return r;
}

// ---------------------------------------------------------------------------
// Weight transpose + fp16 round: WT[n][k] = half(W[k][n])
// block (32,8), grid (N/32, K/32)
// ---------------------------------------------------------------------------
__global__ void transpose_half(const float* __restrict__ W, __half* __restrict__ WT,
                               int K, int N) {
    __shared__ float t[32][33];
    int n0 = blockIdx.x * 32, k0 = blockIdx.y * 32;
    int tx = threadIdx.x, ty = threadIdx.y;
    #pragma unroll
    for (int i = 0; i < 4; i++)
        t[ty + 8*i][tx] = W[(size_t)(k0 + ty + 8*i) * N + n0 + tx];
    __syncthreads();
    int tid = ty * 32 + tx;
    int n_l = tid >> 3;         // 0..31
    int kq  = tid & 7;          // 0..7 -> 4 halves each
    float a = t[kq*4 + 0][n_l];
    float b = t[kq*4 + 1][n_l];
    float c = t[kq*4 + 2][n_l];
    float d = t[kq*4 + 3][n_l];
    *(uint2*)&WT[(size_t)(n0 + n_l) * K + k0 + kq*4] = pack4h(a, b, c, d);
}

// ---------------------------------------------------------------------------
// RMSNorm (stores fp16 xn)
// ---------------------------------------------------------------------------
__global__ void rmsnorm_kernel(const float* __restrict__ x,
                               const float* __restrict__ w,
                               __half* __restrict__ xn) {
    size_t row = blockIdx.x;
    const float4* xr = (const float4*)(x + row * Dm);
    float4 v0 = xr[threadIdx.x];
    float4 v1 = xr[threadIdx.x + 256];
    float ss = v0.x*v0.x + v0.y*v0.y + v0.z*v0.z + v0.w*v0.w
             + v1.x*v1.x + v1.y*v1.y + v1.z*v1.z + v1.w*v1.w;
    #pragma unroll
    for (int o = 16; o > 0; o >>= 1) ss += __shfl_xor_sync(0xffffffffu, ss, o);
    __shared__ float red[8];
    if ((threadIdx.x & 31) == 0) red[threadIdx.x >> 5] = ss;
    __syncthreads();
    float tot = red[0] + red[1] + red[2] + red[3] + red[4] + red[5] + red[6] + red[7];
    float inv = rsqrtf(tot * (1.0f / Dm) + EPSf);

    const float4* wr = (const float4*)w;
    float4 w0 = wr[threadIdx.x];
    float4 w1 = wr[threadIdx.x + 256];
    uint2* orow = (uint2*)(xn + row * Dm);
    orow[threadIdx.x] = pack4h(v0.x * w0.x * inv, v0.y * w0.y * inv,
                               v0.z * w0.z * inv, v0.w * w0.w * inv);
    orow[threadIdx.x + 256] = pack4h(v1.x * w1.x * inv, v1.y * w1.y * inv,
                                     v1.z * w1.z * inv, v1.w * w1.w * inv);
}

// ---------------------------------------------------------------------------
// Causal depthwise conv (K=4) + SiLU (fp16 in, fp16 out; fp32 math)
// ---------------------------------------------------------------------------
__global__ void conv_silu_kernel(const __half* __restrict__ xn,
                                 const float* __restrict__ cw,
                                 const float* __restrict__ cb,
                                 __half* __restrict__ xc, int L) {
    int d  = blockIdx.x * 128 + threadIdx.x;
    int b  = blockIdx.z;
    int l0 = blockIdx.y * 256;
    float w0 = cw[d*KK + 0], w1 = cw[d*KK + 1], w2 = cw[d*KK + 2], w3 = cw[d*KK + 3];
    float bb = cb[d];
    const __half* base = xn + ((size_t)b * L) * Dm + d;
    __half* obase      = xc + ((size_t)b * L) * Dm + d;

    float xm3 = (l0 >= 3) ? __half2float(base[(size_t)(l0 - 3) * Dm]) : 0.0f;
    float xm2 = (l0 >= 2) ? __half2float(base[(size_t)(l0 - 2) * Dm]) : 0.0f;
    float xm1 = (l0 >= 1) ? __half2float(base[(size_t)(l0 - 1) * Dm]) : 0.0f;

    #pragma unroll 8
    for (int l = l0; l < l0 + 256; l++) {
        float xcur = __half2float(base[(size_t)l * Dm]);
        float acc = bb + w0 * xm3 + w1 * xm2 + w2 * xm1 + w3 * xcur;
        float sv = acc * sigmoidf_(acc);
        obase[(size_t)l * Dm] = __float2half_rn(sv);
        xm3 = xm2; xm2 = xm1; xm1 = xcur;
    }
}

// ---------------------------------------------------------------------------
// FP16 GEMM (fp32 accum): C[M,N] = A[M,K] @ WT[N,K]^T (+bias) (+epilogue)
//   MODE 0: +bias   MODE 1: sigmoid(+bias)   MODE 2: +bias+res
// Tiles: BM=128, BN=128, BK=32, m16n8k16, 256 threads (8 warps of 64x32),
// double-buffered cp.async (R7 barrier structure).
// ---------------------------------------------------------------------------
#define FSTR 40                 // halves per SMEM row (40 mod 32-bank safe)
#define FTILE (128 * FSTR)      // 5120 halves per tile

template<int MODE>
__global__ __launch_bounds__(256, 2)
void gemm_fp16(const __half* __restrict__ A, const __half* __restrict__ BT,
               const float* __restrict__ bias, const float* __restrict__ res,
               float* __restrict__ C, int M, int N, int K) {
    __shared__ __half sA[2][FTILE];
    __shared__ __half sB[2][FTILE];

    int tid  = threadIdx.x;
    int wid  = tid >> 5;
    int lane = tid & 31;
    int wm = (wid & 1) * 64;
    int wn = (wid >> 1) * 32;
    int g = lane >> 2;
    int t = lane & 3;

    int bm = blockIdx.y * 128;
    int bn = blockIdx.x * 128;

    const __half* Aptr = A  + (size_t)bm * K;
    const __half* Bptr = BT + (size_t)bn * K;

    float acc[4][4][4];
    #pragma unroll
    for (int i = 0; i < 4; i++)
        #pragma unroll
        for (int j = 0; j < 4; j++)
            #pragma unroll
            for (int q = 0; q < 4; q++) acc[i][j][q] = 0.0f;

    int l_r = tid >> 2;            // 0..63
    int l_c = (tid & 3) * 8;       // halves offset 0/8/16/24

    int NK = K / 32;

    // Prologue: stage 0
    {
        #pragma unroll
        for (int i = 0; i < 2; i++) {
            int r = l_r + 64 * i;
            cp_async16(&sA[0][r * FSTR + l_c], Aptr + (size_t)r * K + l_c);
            cp_async16(&sB[0][r * FSTR + l_c], Bptr + (size_t)r * K + l_c);
        }
        asm volatile("cp.async.commit_group;\n" ::);
    }

    for (int kt = 0; kt < NK; kt++) {
        int buf = kt & 1;
        if (kt + 1 < NK) {
            int k0 = (kt + 1) * 32;
            #pragma unroll
            for (int i = 0; i < 2; i++) {
                int r = l_r + 64 * i;
                cp_async16(&sA[buf ^ 1][r * FSTR + l_c], Aptr + (size_t)r * K + k0 + l_c);
                cp_async16(&sB[buf ^ 1][r * FSTR + l_c], Bptr + (size_t)r * K + k0 + l_c);
            }
            asm volatile("cp.async.commit_group;\n" ::);
            asm volatile("cp.async.wait_group 1;\n" ::);
        } else {
            asm volatile("cp.async.wait_group 0;\n" ::);
        }
        __syncthreads();

        const uint32_t* cA = (const uint32_t*)&sA[buf][0];
        const uint32_t* cB = (const uint32_t*)&sB[buf][0];

        #pragma unroll
        for (int k16 = 0; k16 < 2; k16++) {
            uint32_t af[4][4], bf[4][2];
            #pragma unroll
            for (int mt = 0; mt < 4; mt++) {
                int base = (wm + mt * 16 + g) * 20 + k16 * 8 + t;
                af[mt][0] = cA[base];
                af[mt][1] = cA[base + 160];   // +8 rows
                af[mt][2] = cA[base + 4];     // +8 halves (k+8)
                af[mt][3] = cA[base + 164];
            }
            #pragma unroll
            for (int nt = 0; nt < 4; nt++) {
                int base = (wn + nt * 8 + g) * 20 + k16 * 8 + t;
                bf[nt][0] = cB[base];
                bf[nt][1] = cB[base + 4];
            }
            #pragma unroll
            for (int mt = 0; mt < 4; mt++)
                #pragma unroll
                for (int nt = 0; nt < 4; nt++)
                    mma_f16(acc[mt][nt], af[mt], bf[nt]);
        }
        __syncthreads();
    }

    // Epilogue
    #pragma unroll
    for (int mt = 0; mt < 4; mt++) {
        #pragma unroll
        for (int nt = 0; nt < 4; nt++) {
            int r = bm + wm + mt * 16 + g;
            int c = bn + wn + nt * 8 + 2 * t;
            float b0 = bias[c], b1 = bias[c + 1];
            float v00 = acc[mt][nt][0] + b0;
            float v01 = acc[mt][nt][1] + b1;
            float v10 = acc[mt][nt][2] + b0;
            float v11 = acc[mt][nt][3] + b1;
            if (MODE == 1) {
                v00 = sigmoidf_(v00); v01 = sigmoidf_(v01);
                v10 = sigmoidf_(v10); v11 = sigmoidf_(v11);
            }
            if (MODE == 2) {
                float2 r0 = *(const float2*)&res[(size_t)r * N + c];
                float2 r1 = *(const float2*)&res[(size_t)(r + 8) * N + c];
                v00 += r0.x; v01 += r0.y; v10 += r1.x; v11 += r1.y;
            }
            *(float2*)&C[(size_t)r * N + c]       = make_float2(v00, v01);
            *(float2*)&C[(size_t)(r + 8) * N + c] = make_float2(v10, v11);
        }
    }
}

// ---------------------------------------------------------------------------
// Chunked parallel scan (3 passes). p/gate fp32; xn half; mixed half out.
// ---------------------------------------------------------------------------
__global__ void scan_p1(const float* __restrict__ p,
                        float* __restrict__ Ac, float* __restrict__ Hc,
                        int L, int CL) {
    int chain = blockIdx.x;
    int chunk = blockIdx.y;
    int b = chain / Hh;
    int h = chain % Hh;
    int s = threadIdx.x;

    const size_t pstr = (size_t)Hh * 3 * DSs;
    const float* pb = p + ((size_t)b * L + (size_t)chunk * CL) * pstr
                        + (size_t)h * 3 * DSs + s;

    float A = 1.0f, hl = 0.0f;
    for (int l = 0; l < CL; l += 4) {
        float d0 = __ldg(pb + (size_t)(l+0) * pstr);
        float d1 = __ldg(pb + (size_t)(l+1) * pstr);
        float d2 = __ldg(pb + (size_t)(l+2) * pstr);
        float d3 = __ldg(pb + (size_t)(l+3) * pstr);
        float b0 = __ldg(pb + (size_t)(l+0) * pstr + DSs);
        float b1 = __ldg(pb + (size_t)(l+1) * pstr + DSs);
        float b2 = __ldg(pb + (size_t)(l+2) * pstr + DSs);
        float b3 = __ldg(pb + (size_t)(l+3) * pstr + DSs);
        float s0 = sigmoidf_(d0), s1 = sigmoidf_(d1);
        float s2 = sigmoidf_(d2), s3 = sigmoidf_(d3);
        A *= s0; hl = fmaf(s0, hl, b0);
        A *= s1; hl = fmaf(s1, hl, b1);
        A *= s2; hl = fmaf(s2, hl, b2);
        A *= s3; hl = fmaf(s3, hl, b3);
    }
    size_t idx = ((size_t)chain * NC + chunk) * DSs + s;
    Ac[idx] = A;
    Hc[idx] = hl;
}

__global__ void scan_mid(const float* __restrict__ Ac, const float* __restrict__ Hc,
                         const float* __restrict__ st0,
                         float* __restrict__ hin, float* __restrict__ hlast) {
    int chain = blockIdx.x;
    int s = threadIdx.x;
    float h = st0[(size_t)chain * DSs + s];
    #pragma unroll
    for (int c = 0; c < NC; c++) {
        size_t idx = ((size_t)chain * NC + c) * DSs + s;
        hin[idx] = h;
        h = fmaf(Ac[idx], h, Hc[idx]);
    }
    hlast[(size_t)chain * DSs + s] = h;
}

__global__ void scan_p3(const float* __restrict__ p,
                        const float* __restrict__ gate,
                        const __half* __restrict__ xn,
                        const float* __restrict__ hin,
                        __half* __restrict__ mixed, int L, int CL) {
    int chain = blockIdx.x;
    int chunk = blockIdx.y;
    int b = chain / Hh;
    int h = chain % Hh;
    int s = threadIdx.x;

    float hst = hin[((size_t)chain * NC + chunk) * DSs + s];

    const size_t pstr = (size_t)Hh * 3 * DSs;
    size_t l0 = (size_t)chunk * CL;
    const float* pb = p + ((size_t)b * L + l0) * pstr + (size_t)h * 3 * DSs + s;
    size_t goff = ((size_t)b * L + l0) * Dm + (size_t)h * DSs + s;
    const float* gb = gate + goff;
    const __half* xb = xn + goff;
    __half* mb = mixed + goff;

    for (int l = 0; l < CL; l += 4) {
        float dv[4], bv[4], cv[4], gv[4], xv[4];
        #pragma unroll
        for (int u = 0; u < 4; u++) {
            const float* pp = pb + (size_t)(l + u) * pstr;
            dv[u] = __ldg(pp);
            bv[u] = __ldg(pp + DSs);
            cv[u] = __ldg(pp + 2 * DSs);
            gv[u] = __ldg(gb + (size_t)(l + u) * Dm);
            xv[u] = __half2float(xb[(size_t)(l + u) * Dm]);
        }
        #pragma unroll
        for (int u = 0; u < 4; u++) {
            float dsg = sigmoidf_(dv[u]);
            hst = fmaf(dsg, hst, bv[u]);
            float ssm = cv[u] * hst;
            mb[(size_t)(l + u) * Dm] = __float2half_rn(fmaf(gv[u], ssm - xv[u], xv[u]));
        }
    }
}

// ---------------------------------------------------------------------------
// Launch
// ---------------------------------------------------------------------------
extern "C" void kernel_launch(void* const* d_in, const int* in_sizes, int n_in,
                              void* d_out, int out_size) {
    const float* x      = (const float*)d_in[0];
    const float* state  = (const float*)d_in[1];
    const float* norm_w = (const float*)d_in[2];
    const float* conv_w = (const float*)d_in[3];
    const float* conv_b = (const float*)d_in[4];
    const float* pp_w   = (const float*)d_in[5];
    const float* pp_b   = (const float*)d_in[6];
    const float* gp_w   = (const float*)d_in[7];
    const float* gp_b   = (const float*)d_in[8];
    const float* op_w   = (const float*)d_in[9];
    const float* op_b   = (const float*)d_in[10];
    float* out = (float*)d_out;

    int BL = in_sizes[0] / Dm;                 // 8192
    int Bb = in_sizes[1] / (Hh * DSs);         // 2
    int L  = BL / Bb;                          // 4096
    int NBc = Bb * Hh;                         // 64
    int CL  = L / NC;                          // 128

    float* scratch;
    cudaGetSymbolAddress((void**)&scratch, g_scratch);
    __half* xnH   = (__half*)(scratch + OFF_XNH);
    __half* xcH   = (__half*)(scratch + OFF_XCH);
    __half* mxH   = (__half*)(scratch + OFF_MXH);
    float*  p     = scratch + OFF_P;
    float*  gatep = scratch + OFF_GATE;
    float*  scanA = scratch + OFF_SCANA;
    float*  scanH = scratch + OFF_SCANH;
    float*  scanI = scratch + OFF_SCANI;
    __half* ppH   = (__half*)(scratch + OFF_PPH);
    __half* gpH   = (__half*)(scratch + OFF_GPH);
    __half* opH   = (__half*)(scratch + OFF_OPH);

    // 0) Weight transpose + fp16 round
    transpose_half<<<dim3(P_COLS / 32, Dm / 32), dim3(32, 8)>>>(pp_w, ppH, Dm, P_COLS);
    transpose_half<<<dim3(Dm / 32, Dm / 32), dim3(32, 8)>>>(gp_w, gpH, Dm, Dm);
    transpose_half<<<dim3(Dm / 32, Dm / 32), dim3(32, 8)>>>(op_w, opH, Dm, Dm);

    // 1) RMSNorm (fp16 xn)
    rmsnorm_kernel<<<BL, 256>>>(x, norm_w, xnH);

    // 2) Causal conv + SiLU (fp16 xc)
    conv_silu_kernel<<<dim3(Dm / 128, L / 256, Bb), 128>>>(xnH, conv_w, conv_b, xcH, L);

    // 3) p = xn @ pp_w + pp_b (fp32 out)
    gemm_fp16<0><<<dim3(P_COLS / 128, BL / 128), 256>>>(
        xnH, ppH, pp_b, nullptr, p, BL, P_COLS, Dm);

    // 4) gate = sigmoid(xc @ gp_w + gp_b) (fp32 out)
    gemm_fp16<1><<<dim3(Dm / 128, BL / 128), 256>>>(
        xcH, gpH, gp_b, nullptr, gatep, BL, Dm, Dm);

    // 5) scan (3 passes); h_last to tail of output
    scan_p1<<<dim3(NBc, NC), DSs>>>(p, scanA, scanH, L, CL);
    scan_mid<<<NBc, DSs>>>(scanA, scanH, state, scanI, out + (size_t)BL * Dm);
    scan_p3<<<dim3(NBc, NC), DSs>>>(p, gatep, xnH, scanI, mxH, L, CL);

    // 6) y = mixed @ op_w + op_b + x
    gemm_fp16<2><<<dim3(Dm / 128, BL / 128), 256>>>(
        mxH, opH, op_b, x, out, BL, Dm, Dm);
}

// round 10
// speedup vs baseline: 1.4052x; 1.0097x over previous
#include <cuda_runtime.h>
#include <cuda_fp16.h>
#include <cstdint>
#include <cstddef>
#include <math.h>

// Problem constants
#define Dm   2048
#define Hh   32
#define DSs  64
#define KK   4
#define EPSf 1e-6f
#define NC   32            // scan chunks

// Max sizes (B=2, L=4096)
#define BL_MAX  8192
#define P_COLS  (3*Dm)   // 6144
#define NB_MAX  64       // B*H chains

// Scratch layout (floats)
#define OFF_XNH    ((size_t)0)                               // half[BL*Dm]
#define OFF_XCH    (OFF_XNH + (size_t)BL_MAX*Dm/2)
#define OFF_MXH    (OFF_XCH + (size_t)BL_MAX*Dm/2)
#define OFF_P      (OFF_MXH + (size_t)BL_MAX*Dm/2)
#define OFF_GATE   (OFF_P   + (size_t)BL_MAX*P_COLS)
#define OFF_SCANA  (OFF_GATE + (size_t)BL_MAX*Dm)
#define OFF_SCANH  (OFF_SCANA + (size_t)NB_MAX*NC*DSs)
#define OFF_SCANI  (OFF_SCANH + (size_t)NB_MAX*NC*DSs)
#define OFF_PPH    (OFF_SCANI + (size_t)NB_MAX*NC*DSs)       // half[P_COLS*Dm]
#define OFF_GPH    (OFF_PPH + (size_t)P_COLS*Dm/2)
#define OFF_OPH    (OFF_GPH + (size_t)Dm*Dm/2)
#define SCRATCH_FLOATS (OFF_OPH + (size_t)Dm*Dm/2)

__device__ float g_scratch[SCRATCH_FLOATS];

// ---------------------------------------------------------------------------
// Helpers
// ---------------------------------------------------------------------------
__device__ __forceinline__ void mma_f16(float* c, const uint32_t* a, const uint32_t* b) {
    asm volatile(
        "mma.sync.aligned.m16n8k16.row.col.f32.f16.f16.f32 "
        "{%0,%1,%2,%3}, {%4,%5,%6,%7}, {%8,%9}, {%0,%1,%2,%3};\n"
        : "+f"(c[0]), "+f"(c[1]), "+f"(c[2]), "+f"(c[3])
        : "r"(a[0]), "r"(a[1]), "r"(a[2]), "r"(a[3]),
          "r"(b[0]), "r"(b[1]));
}

__device__ __forceinline__ void ldsm_x4(uint32_t* r, uint32_t addr) {
    asm volatile("ldmatrix.sync.aligned.m8n8.x4.shared.b16 {%0,%1,%2,%3}, [%4];"
        : "=r"(r[0]), "=r"(r[1]), "=r"(r[2]), "=r"(r[3]) : "r"(addr));
}

__device__ __forceinline__ void ldsm_x2(uint32_t* r, uint32_t addr) {
    asm volatile("ldmatrix.sync.aligned.m8n8.x2.shared.b16 {%0,%1}, [%2];"
        : "=r"(r[0]), "=r"(r[1]) : "r"(addr));
}

__device__ __forceinline__ void cp_async16(void* smem, const void* gmem) {
    uint32_t s = (uint32_t)__cvta_generic_to_shared(smem);
    asm volatile("cp.async.cg.shared.global [%0], [%1], 16;\n" :: "r"(s), "l"(gmem));
}

__device__ __forceinline__ float sigmoidf_(float v) {
    return 1.0f / (1.0f + __expf(-v));
}

__device__ __forceinline__ uint2 pack4h(float a, float b, float c, float d) {
    __half2 lo = __floats2half2_rn(a, b);
    __half2 hi = __floats2half2_rn(c, d);
    uint2 r;
    r.x = *(uint32_t*)&lo;
    r.y = *(uint32_t*)&hi;
    return r;
}

// ---------------------------------------------------------------------------
// Weight transpose + fp16 round: WT[n][k] = half(W[k][n])
// ---------------------------------------------------------------------------
__global__ void transpose_half(const float* __restrict__ W, __half* __restrict__ WT,
                               int K, int N) {
    __shared__ float t[32][33];
    int n0 = blockIdx.x * 32, k0 = blockIdx.y * 32;
    int tx = threadIdx.x, ty = threadIdx.y;
    #pragma unroll
    for (int i = 0; i < 4; i++)
        t[ty + 8*i][tx] = W[(size_t)(k0 + ty + 8*i) * N + n0 + tx];
    __syncthreads();
    int tid = ty * 32 + tx;
    int n_l = tid >> 3;         // 0..31
    int kq  = tid & 7;          // 0..7 -> 4 halves each
    float a = t[kq*4 + 0][n_l];
    float b = t[kq*4 + 1][n_l];
    float c = t[kq*4 + 2][n_l];
    float d = t[kq*4 + 3][n_l];
    *(uint2*)&WT[(size_t)(n0 + n_l) * K + k0 + kq*4] = pack4h(a, b, c, d);
}

// ---------------------------------------------------------------------------
// RMSNorm (stores fp16 xn)
// ---------------------------------------------------------------------------
__global__ void rmsnorm_kernel(const float* __restrict__ x,
                               const float* __restrict__ w,
                               __half* __restrict__ xn) {
    size_t row = blockIdx.x;
    const float4* xr = (const float4*)(x + row * Dm);
    float4 v0 = xr[threadIdx.x];
    float4 v1 = xr[threadIdx.x + 256];
    float ss = v0.x*v0.x + v0.y*v0.y + v0.z*v0.z + v0.w*v0.w
             + v1.x*v1.x + v1.y*v1.y + v1.z*v1.z + v1.w*v1.w;
    #pragma unroll
    for (int o = 16; o > 0; o >>= 1) ss += __shfl_xor_sync(0xffffffffu, ss, o);
    __shared__ float red[8];
    if ((threadIdx.x & 31) == 0) red[threadIdx.x >> 5] = ss;
    __syncthreads();
    float tot = red[0] + red[1] + red[2] + red[3] + red[4] + red[5] + red[6] + red[7];
    float inv = rsqrtf(tot * (1.0f / Dm) + EPSf);

    const float4* wr = (const float4*)w;
    float4 w0 = wr[threadIdx.x];
    float4 w1 = wr[threadIdx.x + 256];
    uint2* orow = (uint2*)(xn + row * Dm);
    orow[threadIdx.x] = pack4h(v0.x * w0.x * inv, v0.y * w0.y * inv,
                               v0.z * w0.z * inv, v0.w * w0.w * inv);
    orow[threadIdx.x + 256] = pack4h(v1.x * w1.x * inv, v1.y * w1.y * inv,
                                     v1.z * w1.z * inv, v1.w * w1.w * inv);
}

// ---------------------------------------------------------------------------
// Causal depthwise conv (K=4) + SiLU (fp16 in, fp16 out; fp32 math)
// ---------------------------------------------------------------------------
__global__ void conv_silu_kernel(const __half* __restrict__ xn,
                                 const float* __restrict__ cw,
                                 const float* __restrict__ cb,
                                 __half* __restrict__ xc, int L) {
    int d  = blockIdx.x * 128 + threadIdx.x;
    int b  = blockIdx.z;
    int l0 = blockIdx.y * 256;
    float w0 = cw[d*KK + 0], w1 = cw[d*KK + 1], w2 = cw[d*KK + 2], w3 = cw[d*KK + 3];
    float bb = cb[d];
    const __half* base = xn + ((size_t)b * L) * Dm + d;
    __half* obase      = xc + ((size_t)b * L) * Dm + d;

    float xm3 = (l0 >= 3) ? __half2float(base[(size_t)(l0 - 3) * Dm]) : 0.0f;
    float xm2 = (l0 >= 2) ? __half2float(base[(size_t)(l0 - 2) * Dm]) : 0.0f;
    float xm1 = (l0 >= 1) ? __half2float(base[(size_t)(l0 - 1) * Dm]) : 0.0f;

    #pragma unroll 8
    for (int l = l0; l < l0 + 256; l++) {
        float xcur = __half2float(base[(size_t)l * Dm]);
        float acc = bb + w0 * xm3 + w1 * xm2 + w2 * xm1 + w3 * xcur;
        float sv = acc * sigmoidf_(acc);
        obase[(size_t)l * Dm] = __float2half_rn(sv);
        xm3 = xm2; xm2 = xm1; xm1 = xcur;
    }
}

// ---------------------------------------------------------------------------
// FP16 GEMM (fp32 accum), ldmatrix fragment loads.
//   MODE 0: +bias   MODE 1: sigmoid(+bias)   MODE 2: +bias+res
// Tiles: BM=128, BN=128, BK=32, m16n8k16, 256 threads (8 warps of 64x32),
// double-buffered cp.async.
// ---------------------------------------------------------------------------
#define FSTR 40                 // halves per SMEM row
#define FTILE (128 * FSTR)      // 5120 halves per tile

template<int MODE>
__global__ __launch_bounds__(256, 2)
void gemm_fp16(const __half* __restrict__ A, const __half* __restrict__ BT,
               const float* __restrict__ bias, const float* __restrict__ res,
               float* __restrict__ C, int M, int N, int K) {
    __shared__ __half sA[2][FTILE];
    __shared__ __half sB[2][FTILE];

    int tid  = threadIdx.x;
    int wid  = tid >> 5;
    int lane = tid & 31;
    int wm = (wid & 1) * 64;
    int wn = (wid >> 1) * 32;
    int g = lane >> 2;
    int t = lane & 3;

    int bm = blockIdx.y * 128;
    int bn = blockIdx.x * 128;

    const __half* Aptr = A  + (size_t)bm * K;
    const __half* Bptr = BT + (size_t)bn * K;

    float acc[4][4][4];
    #pragma unroll
    for (int i = 0; i < 4; i++)
        #pragma unroll
        for (int j = 0; j < 4; j++)
            #pragma unroll
            for (int q = 0; q < 4; q++) acc[i][j][q] = 0.0f;

    int l_r = tid >> 2;            // 0..63
    int l_c = (tid & 3) * 8;       // halves offset 0/8/16/24

    // ldmatrix per-lane base offsets (in bytes) within a tile
    uint32_t sA0 = (uint32_t)__cvta_generic_to_shared(&sA[0][0]);
    uint32_t sB0 = (uint32_t)__cvta_generic_to_shared(&sB[0][0]);
    // A.x4: row = wm + mt*16 + (lane&15), col halves = (lane>>4)*8 + k16*16
    uint32_t a_off = (uint32_t)(((wm + (lane & 15)) * FSTR + ((lane >> 4) << 3)) * 2);
    // B.x2: row = wn + nt*8 + (lane&7), col halves = ((lane>>3)&1)*8 + k16*16
    uint32_t b_off = (uint32_t)(((wn + (lane & 7)) * FSTR + (((lane >> 3) & 1) << 3)) * 2);

    int NK = K / 32;

    // Prologue: stage 0
    {
        #pragma unroll
        for (int i = 0; i < 2; i++) {
            int r = l_r + 64 * i;
            cp_async16(&sA[0][r * FSTR + l_c], Aptr + (size_t)r * K + l_c);
            cp_async16(&sB[0][r * FSTR + l_c], Bptr + (size_t)r * K + l_c);
        }
        asm volatile("cp.async.commit_group;\n" ::);
    }

    for (int kt = 0; kt < NK; kt++) {
        int buf = kt & 1;
        if (kt + 1 < NK) {
            int k0 = (kt + 1) * 32;
            #pragma unroll
            for (int i = 0; i < 2; i++) {
                int r = l_r + 64 * i;
                cp_async16(&sA[buf ^ 1][r * FSTR + l_c], Aptr + (size_t)r * K + k0 + l_c);
                cp_async16(&sB[buf ^ 1][r * FSTR + l_c], Bptr + (size_t)r * K + k0 + l_c);
            }
            asm volatile("cp.async.commit_group;\n" ::);
            asm volatile("cp.async.wait_group 1;\n" ::);
        } else {
            asm volatile("cp.async.wait_group 0;\n" ::);
        }
        __syncthreads();

        uint32_t aBase = sA0 + (uint32_t)(buf * FTILE * 2) + a_off;
        uint32_t bBase = sB0 + (uint32_t)(buf * FTILE * 2) + b_off;

        #pragma unroll
        for (int k16 = 0; k16 < 2; k16++) {
            uint32_t af[4][4], bf[4][2];
            #pragma unroll
            for (int mt = 0; mt < 4; mt++)
                ldsm_x4(af[mt], aBase + (uint32_t)(mt * 16 * FSTR * 2 + k16 * 32));
            #pragma unroll
            for (int nt = 0; nt < 4; nt++)
                ldsm_x2(bf[nt], bBase + (uint32_t)(nt * 8 * FSTR * 2 + k16 * 32));
            #pragma unroll
            for (int mt = 0; mt < 4; mt++)
                #pragma unroll
                for (int nt = 0; nt < 4; nt++)
                    mma_f16(acc[mt][nt], af[mt], bf[nt]);
        }
        __syncthreads();
    }

    // Epilogue
    #pragma unroll
    for (int mt = 0; mt < 4; mt++) {
        #pragma unroll
        for (int nt = 0; nt < 4; nt++) {
            int r = bm + wm + mt * 16 + g;
            int c = bn + wn + nt * 8 + 2 * t;
            float b0 = bias[c], b1 = bias[c + 1];
            float v00 = acc[mt][nt][0] + b0;
            float v01 = acc[mt][nt][1] + b1;
            float v10 = acc[mt][nt][2] + b0;
            float v11 = acc[mt][nt][3] + b1;
            if (MODE == 1) {
                v00 = sigmoidf_(v00); v01 = sigmoidf_(v01);
                v10 = sigmoidf_(v10); v11 = sigmoidf_(v11);
            }
            if (MODE == 2) {
                float2 r0 = *(const float2*)&res[(size_t)r * N + c];
                float2 r1 = *(const float2*)&res[(size_t)(r + 8) * N + c];
                v00 += r0.x; v01 += r0.y; v10 += r1.x; v11 += r1.y;
            }
            *(float2*)&C[(size_t)r * N + c]       = make_float2(v00, v01);
            *(float2*)&C[(size_t)(r + 8) * N + c] = make_float2(v10, v11);
        }
    }
}

// ---------------------------------------------------------------------------
// Chunked parallel scan (3 passes). p/gate fp32; xn half; mixed half out.
// ---------------------------------------------------------------------------
__global__ void scan_p1(const float* __restrict__ p,
                        float* __restrict__ Ac, float* __restrict__ Hc,
                        int L, int CL) {
    int chain = blockIdx.x;
    int chunk = blockIdx.y;
    int b = chain / Hh;
    int h = chain % Hh;
    int s = threadIdx.x;

    const size_t pstr = (size_t)Hh * 3 * DSs;
    const float* pb = p + ((size_t)b * L + (size_t)chunk * CL) * pstr
                        + (size_t)h * 3 * DSs + s;

    float A = 1.0f, hl = 0.0f;
    for (int l = 0; l < CL; l += 4) {
        float d0 = __ldg(pb + (size_t)(l+0) * pstr);
        float d1 = __ldg(pb + (size_t)(l+1) * pstr);
        float d2 = __ldg(pb + (size_t)(l+2) * pstr);
        float d3 = __ldg(pb + (size_t)(l+3) * pstr);
        float b0 = __ldg(pb + (size_t)(l+0) * pstr + DSs);
        float b1 = __ldg(pb + (size_t)(l+1) * pstr + DSs);
        float b2 = __ldg(pb + (size_t)(l+2) * pstr + DSs);
        float b3 = __ldg(pb + (size_t)(l+3) * pstr + DSs);
        float s0 = sigmoidf_(d0), s1 = sigmoidf_(d1);
        float s2 = sigmoidf_(d2), s3 = sigmoidf_(d3);
        A *= s0; hl = fmaf(s0, hl, b0);
        A *= s1; hl = fmaf(s1, hl, b1);
        A *= s2; hl = fmaf(s2, hl, b2);
        A *= s3; hl = fmaf(s3, hl, b3);
    }
    size_t idx = ((size_t)chain * NC + chunk) * DSs + s;
    Ac[idx] = A;
    Hc[idx] = hl;
}

__global__ void scan_mid(const float* __restrict__ Ac, const float* __restrict__ Hc,
                         const float* __restrict__ st0,
                         float* __restrict__ hin, float* __restrict__ hlast) {
    int chain = blockIdx.x;
    int s = threadIdx.x;
    float h = st0[(size_t)chain * DSs + s];
    #pragma unroll
    for (int c = 0; c < NC; c++) {
        size_t idx = ((size_t)chain * NC + c) * DSs + s;
        hin[idx] = h;
        h = fmaf(Ac[idx], h, Hc[idx]);
    }
    hlast[(size_t)chain * DSs + s] = h;
}

__global__ void scan_p3(const float* __restrict__ p,
                        const float* __restrict__ gate,
                        const __half* __restrict__ xn,
                        const float* __restrict__ hin,
                        __half* __restrict__ mixed, int L, int CL) {
    int chain = blockIdx.x;
    int chunk = blockIdx.y;
    int b = chain / Hh;
    int h = chain % Hh;
    int s = threadIdx.x;

    float hst = hin[((size_t)chain * NC + chunk) * DSs + s];

    const size_t pstr = (size_t)Hh * 3 * DSs;
    size_t l0 = (size_t)chunk * CL;
    const float* pb = p + ((size_t)b * L + l0) * pstr + (size_t)h * 3 * DSs + s;
    size_t goff = ((size_t)b * L + l0) * Dm + (size_t)h * DSs + s;
    const float* gb = gate + goff;
    const __half* xb = xn + goff;
    __half* mb = mixed + goff;

    for (int l = 0; l < CL; l += 4) {
        float dv[4], bv[4], cv[4], gv[4], xv[4];
        #pragma unroll
        for (int u = 0; u < 4; u++) {
            const float* pp = pb + (size_t)(l + u) * pstr;
            dv[u] = __ldg(pp);
            bv[u] = __ldg(pp + DSs);
            cv[u] = __ldg(pp + 2 * DSs);
            gv[u] = __ldg(gb + (size_t)(l + u) * Dm);
            xv[u] = __half2float(xb[(size_t)(l + u) * Dm]);
        }
        #pragma unroll
        for (int u = 0; u < 4; u++) {
            float dsg = sigmoidf_(dv[u]);
            hst = fmaf(dsg, hst, bv[u]);
            float ssm = cv[u] * hst;
            mb[(size_t)(l + u) * Dm] = __float2half_rn(fmaf(gv[u], ssm - xv[u], xv[u]));
        }
    }
}

// ---------------------------------------------------------------------------
// Launch
// ---------------------------------------------------------------------------
extern "C" void kernel_launch(void* const* d_in, const int* in_sizes, int n_in,
                              void* d_out, int out_size) {
    const float* x      = (const float*)d_in[0];
    const float* state  = (const float*)d_in[1];
    const float* norm_w = (const float*)d_in[2];
    const float* conv_w = (const float*)d_in[3];
    const float* conv_b = (const float*)d_in[4];
    const float* pp_w   = (const float*)d_in[5];
    const float* pp_b   = (const float*)d_in[6];
    const float* gp_w   = (const float*)d_in[7];
    const float* gp_b   = (const float*)d_in[8];
    const float* op_w   = (const float*)d_in[9];
    const float* op_b   = (const float*)d_in[10];
    float* out = (float*)d_out;

    int BL = in_sizes[0] / Dm;                 // 8192
    int Bb = in_sizes[1] / (Hh * DSs);         // 2
    int L  = BL / Bb;                          // 4096
    int NBc = Bb * Hh;                         // 64
    int CL  = L / NC;                          // 128

    float* scratch;
    cudaGetSymbolAddress((void**)&scratch, g_scratch);
    __half* xnH   = (__half*)(scratch + OFF_XNH);
    __half* xcH   = (__half*)(scratch + OFF_XCH);
    __half* mxH   = (__half*)(scratch + OFF_MXH);
    float*  p     = scratch + OFF_P;
    float*  gatep = scratch + OFF_GATE;
    float*  scanA = scratch + OFF_SCANA;
    float*  scanH = scratch + OFF_SCANH;
    float*  scanI = scratch + OFF_SCANI;
    __half* ppH   = (__half*)(scratch + OFF_PPH);
    __half* gpH   = (__half*)(scratch + OFF_GPH);
    __half* opH   = (__half*)(scratch + OFF_OPH);

    // 0) Weight transpose + fp16 round
    transpose_half<<<dim3(P_COLS / 32, Dm / 32), dim3(32, 8)>>>(pp_w, ppH, Dm, P_COLS);
    transpose_half<<<dim3(Dm / 32, Dm / 32), dim3(32, 8)>>>(gp_w, gpH, Dm, Dm);
    transpose_half<<<dim3(Dm / 32, Dm / 32), dim3(32, 8)>>>(op_w, opH, Dm, Dm);

    // 1) RMSNorm (fp16 xn)
    rmsnorm_kernel<<<BL, 256>>>(x, norm_w, xnH);

    // 2) Causal conv + SiLU (fp16 xc)
    conv_silu_kernel<<<dim3(Dm / 128, L / 256, Bb), 128>>>(xnH, conv_w, conv_b, xcH, L);

    // 3) p = xn @ pp_w + pp_b (fp32 out)
    gemm_fp16<0><<<dim3(P_COLS / 128, BL / 128), 256>>>(
        xnH, ppH, pp_b, nullptr, p, BL, P_COLS, Dm);

    // 4) gate = sigmoid(xc @ gp_w + gp_b) (fp32 out)
    gemm_fp16<1><<<dim3(Dm / 128, BL / 128), 256>>>(
        xcH, gpH, gp_b, nullptr, gatep, BL, Dm, Dm);

    // 5) scan (3 passes); h_last to tail of output
    scan_p1<<<dim3(NBc, NC), DSs>>>(p, scanA, scanH, L, CL);
    scan_mid<<<NBc, DSs>>>(scanA, scanH, state, scanI, out + (size_t)BL * Dm);
    scan_p3<<<dim3(NBc, NC), DSs>>>(p, gatep, xnH, scanI, mxH, L, CL);

    // 6) y = mixed @ op_w + op_b + x
    gemm_fp16<2><<<dim3(Dm / 128, BL / 128), 256>>>(
        mxH, opH, op_b, x, out, BL, Dm, Dm);
}

// round 11
// speedup vs baseline: 1.4307x; 1.0182x over previous
#include <cuda_runtime.h>
#include <cuda_fp16.h>
#include <cstdint>
#include <cstddef>
#include <math.h>

// Problem constants
#define Dm   2048
#define Hh   32
#define DSs  64
#define KK   4
#define EPSf 1e-6f
#define NC   64            // scan chunks

// Max sizes (B=2, L=4096)
#define BL_MAX  8192
#define P_COLS  (3*Dm)   // 6144
#define NB_MAX  64       // B*H chains

// Scratch layout (in floats)
#define OFF_XNH    ((size_t)0)                               // half[BL*Dm]
#define OFF_XCH    (OFF_XNH + (size_t)BL_MAX*Dm/2)
#define OFF_MXH    (OFF_XCH + (size_t)BL_MAX*Dm/2)
#define OFF_PH     (OFF_MXH + (size_t)BL_MAX*Dm/2)           // half[BL*P_COLS]
#define OFF_GATEH  (OFF_PH  + (size_t)BL_MAX*P_COLS/2)       // half[BL*Dm]
#define OFF_SCANA  (OFF_GATEH + (size_t)BL_MAX*Dm/2)
#define OFF_SCANH  (OFF_SCANA + (size_t)NB_MAX*NC*DSs)
#define OFF_SCANI  (OFF_SCANH + (size_t)NB_MAX*NC*DSs)
#define OFF_PPH    (OFF_SCANI + (size_t)NB_MAX*NC*DSs)       // half[P_COLS*Dm]
#define OFF_GPH    (OFF_PPH + (size_t)P_COLS*Dm/2)
#define OFF_OPH    (OFF_GPH + (size_t)Dm*Dm/2)
#define SCRATCH_FLOATS (OFF_OPH + (size_t)Dm*Dm/2)

__device__ float g_scratch[SCRATCH_FLOATS];

// ---------------------------------------------------------------------------
// Helpers
// ---------------------------------------------------------------------------
__device__ __forceinline__ void mma_f16(float* c, const uint32_t* a, const uint32_t* b) {
    asm volatile(
        "mma.sync.aligned.m16n8k16.row.col.f32.f16.f16.f32 "
        "{%0,%1,%2,%3}, {%4,%5,%6,%7}, {%8,%9}, {%0,%1,%2,%3};\n"
        : "+f"(c[0]), "+f"(c[1]), "+f"(c[2]), "+f"(c[3])
        : "r"(a[0]), "r"(a[1]), "r"(a[2]), "r"(a[3]),
          "r"(b[0]), "r"(b[1]));
}

__device__ __forceinline__ void ldsm_x4(uint32_t* r, uint32_t addr) {
    asm volatile("ldmatrix.sync.aligned.m8n8.x4.shared.b16 {%0,%1,%2,%3}, [%4];"
        : "=r"(r[0]), "=r"(r[1]), "=r"(r[2]), "=r"(r[3]) : "r"(addr));
}

__device__ __forceinline__ void ldsm_x2(uint32_t* r, uint32_t addr) {
    asm volatile("ldmatrix.sync.aligned.m8n8.x2.shared.b16 {%0,%1}, [%2];"
        : "=r"(r[0]), "=r"(r[1]) : "r"(addr));
}

__device__ __forceinline__ void cp_async16(void* smem, const void* gmem) {
    uint32_t s = (uint32_t)__cvta_generic_to_shared(smem);
    asm volatile("cp.async.cg.shared.global [%0], [%1], 16;\n" :: "r"(s), "l"(gmem));
}

__device__ __forceinline__ float sigmoidf_(float v) {
    return 1.0f / (1.0f + __expf(-v));
}

__device__ __forceinline__ uint2 pack4h(float a, float b, float c, float d) {
    __half2 lo = __floats2half2_rn(a, b);
    __half2 hi = __floats2half2_rn(c, d);
    uint2 r;
    r.x = *(uint32_t*)&lo;
    r.y = *(uint32_t*)&hi;
    return r;
}

// ---------------------------------------------------------------------------
// Fused weight transpose + fp16 round for all three weights (z-indexed).
// WT[n][k] = half(W[k][n]); K = 2048 for all; N = 6144 (pp) or 2048 (gp/op).
// grid (192, 64, 3), block (32,8)
// ---------------------------------------------------------------------------
__global__ void transpose_half_all(const float* __restrict__ pp,
                                   const float* __restrict__ gp,
                                   const float* __restrict__ op,
                                   __half* __restrict__ ppT,
                                   __half* __restrict__ gpT,
                                   __half* __restrict__ opT) {
    const float* W;
    __half* WT;
    int N;
    if (blockIdx.z == 0)      { W = pp; WT = ppT; N = P_COLS; }
    else if (blockIdx.z == 1) { W = gp; WT = gpT; N = Dm; }
    else                      { W = op; WT = opT; N = Dm; }
    if (blockIdx.x * 32 >= N) return;

    __shared__ float t[32][33];
    int n0 = blockIdx.x * 32, k0 = blockIdx.y * 32;
    int tx = threadIdx.x, ty = threadIdx.y;
    #pragma unroll
    for (int i = 0; i < 4; i++)
        t[ty + 8*i][tx] = W[(size_t)(k0 + ty + 8*i) * N + n0 + tx];
    __syncthreads();
    int tid = ty * 32 + tx;
    int n_l = tid >> 3;
    int kq  = tid & 7;
    float a = t[kq*4 + 0][n_l];
    float b = t[kq*4 + 1][n_l];
    float c = t[kq*4 + 2][n_l];
    float d = t[kq*4 + 3][n_l];
    *(uint2*)&WT[(size_t)(n0 + n_l) * Dm + k0 + kq*4] = pack4h(a, b, c, d);
}

// ---------------------------------------------------------------------------
// RMSNorm (stores fp16 xn)
// ---------------------------------------------------------------------------
__global__ void rmsnorm_kernel(const float* __restrict__ x,
                               const float* __restrict__ w,
                               __half* __restrict__ xn) {
    size_t row = blockIdx.x;
    const float4* xr = (const float4*)(x + row * Dm);
    float4 v0 = xr[threadIdx.x];
    float4 v1 = xr[threadIdx.x + 256];
    float ss = v0.x*v0.x + v0.y*v0.y + v0.z*v0.z + v0.w*v0.w
             + v1.x*v1.x + v1.y*v1.y + v1.z*v1.z + v1.w*v1.w;
    #pragma unroll
    for (int o = 16; o > 0; o >>= 1) ss += __shfl_xor_sync(0xffffffffu, ss, o);
    __shared__ float red[8];
    if ((threadIdx.x & 31) == 0) red[threadIdx.x >> 5] = ss;
    __syncthreads();
    float tot = red[0] + red[1] + red[2] + red[3] + red[4] + red[5] + red[6] + red[7];
    float inv = rsqrtf(tot * (1.0f / Dm) + EPSf);

    const float4* wr = (const float4*)w;
    float4 w0 = wr[threadIdx.x];
    float4 w1 = wr[threadIdx.x + 256];
    uint2* orow = (uint2*)(xn + row * Dm);
    orow[threadIdx.x] = pack4h(v0.x * w0.x * inv, v0.y * w0.y * inv,
                               v0.z * w0.z * inv, v0.w * w0.w * inv);
    orow[threadIdx.x + 256] = pack4h(v1.x * w1.x * inv, v1.y * w1.y * inv,
                                     v1.z * w1.z * inv, v1.w * w1.w * inv);
}

// ---------------------------------------------------------------------------
// Causal depthwise conv (K=4) + SiLU (fp16 in, fp16 out; fp32 math)
// ---------------------------------------------------------------------------
__global__ void conv_silu_kernel(const __half* __restrict__ xn,
                                 const float* __restrict__ cw,
                                 const float* __restrict__ cb,
                                 __half* __restrict__ xc, int L) {
    int d  = blockIdx.x * 128 + threadIdx.x;
    int b  = blockIdx.z;
    int l0 = blockIdx.y * 256;
    float w0 = cw[d*KK + 0], w1 = cw[d*KK + 1], w2 = cw[d*KK + 2], w3 = cw[d*KK + 3];
    float bb = cb[d];
    const __half* base = xn + ((size_t)b * L) * Dm + d;
    __half* obase      = xc + ((size_t)b * L) * Dm + d;

    float xm3 = (l0 >= 3) ? __half2float(base[(size_t)(l0 - 3) * Dm]) : 0.0f;
    float xm2 = (l0 >= 2) ? __half2float(base[(size_t)(l0 - 2) * Dm]) : 0.0f;
    float xm1 = (l0 >= 1) ? __half2float(base[(size_t)(l0 - 1) * Dm]) : 0.0f;

    #pragma unroll 8
    for (int l = l0; l < l0 + 256; l++) {
        float xcur = __half2float(base[(size_t)l * Dm]);
        float acc = bb + w0 * xm3 + w1 * xm2 + w2 * xm1 + w3 * xcur;
        float sv = acc * sigmoidf_(acc);
        obase[(size_t)l * Dm] = __float2half_rn(sv);
        xm3 = xm2; xm2 = xm1; xm1 = xcur;
    }
}

// ---------------------------------------------------------------------------
// FP16 GEMM (fp32 accum), ldmatrix fragment loads.
//   MODE 0: +bias -> half out (p)
//   MODE 1: sigmoid(+bias) -> half out (gate)
//   MODE 2: +bias+res -> float out (y)
// Tiles: BM=128, BN=128, BK=32, m16n8k16, 256 threads, double-buffered.
// ---------------------------------------------------------------------------
#define FSTR 40                 // halves per SMEM row
#define FTILE (128 * FSTR)      // 5120 halves per tile

template<int MODE>
__global__ __launch_bounds__(256, 2)
void gemm_fp16(const __half* __restrict__ A, const __half* __restrict__ BT,
               const float* __restrict__ bias, const float* __restrict__ res,
               void* __restrict__ Cout, int M, int N, int K) {
    __shared__ __half sA[2][FTILE];
    __shared__ __half sB[2][FTILE];

    int tid  = threadIdx.x;
    int wid  = tid >> 5;
    int lane = tid & 31;
    int wm = (wid & 1) * 64;
    int wn = (wid >> 1) * 32;
    int g = lane >> 2;
    int t = lane & 3;

    int bm = blockIdx.y * 128;
    int bn = blockIdx.x * 128;

    const __half* Aptr = A  + (size_t)bm * K;
    const __half* Bptr = BT + (size_t)bn * K;

    float acc[4][4][4];
    #pragma unroll
    for (int i = 0; i < 4; i++)
        #pragma unroll
        for (int j = 0; j < 4; j++)
            #pragma unroll
            for (int q = 0; q < 4; q++) acc[i][j][q] = 0.0f;

    int l_r = tid >> 2;            // 0..63
    int l_c = (tid & 3) * 8;       // halves offset 0/8/16/24

    uint32_t sA0 = (uint32_t)__cvta_generic_to_shared(&sA[0][0]);
    uint32_t sB0 = (uint32_t)__cvta_generic_to_shared(&sB[0][0]);
    uint32_t a_off = (uint32_t)(((wm + (lane & 15)) * FSTR + ((lane >> 4) << 3)) * 2);
    uint32_t b_off = (uint32_t)(((wn + (lane & 7)) * FSTR + (((lane >> 3) & 1) << 3)) * 2);

    int NK = K / 32;

    // Prologue: stage 0
    {
        #pragma unroll
        for (int i = 0; i < 2; i++) {
            int r = l_r + 64 * i;
            cp_async16(&sA[0][r * FSTR + l_c], Aptr + (size_t)r * K + l_c);
            cp_async16(&sB[0][r * FSTR + l_c], Bptr + (size_t)r * K + l_c);
        }
        asm volatile("cp.async.commit_group;\n" ::);
    }

    for (int kt = 0; kt < NK; kt++) {
        int buf = kt & 1;
        if (kt + 1 < NK) {
            int k0 = (kt + 1) * 32;
            #pragma unroll
            for (int i = 0; i < 2; i++) {
                int r = l_r + 64 * i;
                cp_async16(&sA[buf ^ 1][r * FSTR + l_c], Aptr + (size_t)r * K + k0 + l_c);
                cp_async16(&sB[buf ^ 1][r * FSTR + l_c], Bptr + (size_t)r * K + k0 + l_c);
            }
            asm volatile("cp.async.commit_group;\n" ::);
            asm volatile("cp.async.wait_group 1;\n" ::);
        } else {
            asm volatile("cp.async.wait_group 0;\n" ::);
        }
        __syncthreads();

        uint32_t aBase = sA0 + (uint32_t)(buf * FTILE * 2) + a_off;
        uint32_t bBase = sB0 + (uint32_t)(buf * FTILE * 2) + b_off;

        #pragma unroll
        for (int k16 = 0; k16 < 2; k16++) {
            uint32_t af[4][4], bf[4][2];
            #pragma unroll
            for (int mt = 0; mt < 4; mt++)
                ldsm_x4(af[mt], aBase + (uint32_t)(mt * 16 * FSTR * 2 + k16 * 32));
            #pragma unroll
            for (int nt = 0; nt < 4; nt++)
                ldsm_x2(bf[nt], bBase + (uint32_t)(nt * 8 * FSTR * 2 + k16 * 32));
            #pragma unroll
            for (int mt = 0; mt < 4; mt++)
                #pragma unroll
                for (int nt = 0; nt < 4; nt++)
                    mma_f16(acc[mt][nt], af[mt], bf[nt]);
        }
        __syncthreads();
    }

    // Epilogue
    #pragma unroll
    for (int mt = 0; mt < 4; mt++) {
        #pragma unroll
        for (int nt = 0; nt < 4; nt++) {
            int r = bm + wm + mt * 16 + g;
            int c = bn + wn + nt * 8 + 2 * t;
            float b0 = bias[c], b1 = bias[c + 1];
            float v00 = acc[mt][nt][0] + b0;
            float v01 = acc[mt][nt][1] + b1;
            float v10 = acc[mt][nt][2] + b0;
            float v11 = acc[mt][nt][3] + b1;
            if (MODE == 1) {
                v00 = sigmoidf_(v00); v01 = sigmoidf_(v01);
                v10 = sigmoidf_(v10); v11 = sigmoidf_(v11);
            }
            if (MODE == 2) {
                float* C = (float*)Cout;
                float2 r0 = *(const float2*)&res[(size_t)r * N + c];
                float2 r1 = *(const float2*)&res[(size_t)(r + 8) * N + c];
                v00 += r0.x; v01 += r0.y; v10 += r1.x; v11 += r1.y;
                *(float2*)&C[(size_t)r * N + c]       = make_float2(v00, v01);
                *(float2*)&C[(size_t)(r + 8) * N + c] = make_float2(v10, v11);
            } else {
                __half* C = (__half*)Cout;
                *(__half2*)&C[(size_t)r * N + c]       = __floats2half2_rn(v00, v01);
                *(__half2*)&C[(size_t)(r + 8) * N + c] = __floats2half2_rn(v10, v11);
            }
        }
    }
}

// ---------------------------------------------------------------------------
// Chunked parallel scan (3 passes). p half, gate half, xn half, mixed half.
// ---------------------------------------------------------------------------
__global__ void scan_p1(const __half* __restrict__ p,
                        float* __restrict__ Ac, float* __restrict__ Hc,
                        int L, int CL) {
    int chain = blockIdx.x;
    int chunk = blockIdx.y;
    int b = chain / Hh;
    int h = chain % Hh;
    int s = threadIdx.x;

    const size_t pstr = (size_t)Hh * 3 * DSs;
    const __half* pb = p + ((size_t)b * L + (size_t)chunk * CL) * pstr
                         + (size_t)h * 3 * DSs + s;

    float A = 1.0f, hl = 0.0f;
    for (int l = 0; l < CL; l += 4) {
        float d0 = __half2float(__ldg(pb + (size_t)(l+0) * pstr));
        float d1 = __half2float(__ldg(pb + (size_t)(l+1) * pstr));
        float d2 = __half2float(__ldg(pb + (size_t)(l+2) * pstr));
        float d3 = __half2float(__ldg(pb + (size_t)(l+3) * pstr));
        float b0 = __half2float(__ldg(pb + (size_t)(l+0) * pstr + DSs));
        float b1 = __half2float(__ldg(pb + (size_t)(l+1) * pstr + DSs));
        float b2 = __half2float(__ldg(pb + (size_t)(l+2) * pstr + DSs));
        float b3 = __half2float(__ldg(pb + (size_t)(l+3) * pstr + DSs));
        float s0 = sigmoidf_(d0), s1 = sigmoidf_(d1);
        float s2 = sigmoidf_(d2), s3 = sigmoidf_(d3);
        A *= s0; hl = fmaf(s0, hl, b0);
        A *= s1; hl = fmaf(s1, hl, b1);
        A *= s2; hl = fmaf(s2, hl, b2);
        A *= s3; hl = fmaf(s3, hl, b3);
    }
    size_t idx = ((size_t)chain * NC + chunk) * DSs + s;
    Ac[idx] = A;
    Hc[idx] = hl;
}

__global__ void scan_mid(const float* __restrict__ Ac, const float* __restrict__ Hc,
                         const float* __restrict__ st0,
                         float* __restrict__ hin, float* __restrict__ hlast) {
    int chain = blockIdx.x;
    int s = threadIdx.x;
    float h = st0[(size_t)chain * DSs + s];
    #pragma unroll
    for (int c = 0; c < NC; c++) {
        size_t idx = ((size_t)chain * NC + c) * DSs + s;
        hin[idx] = h;
        h = fmaf(Ac[idx], h, Hc[idx]);
    }
    hlast[(size_t)chain * DSs + s] = h;
}

__global__ void scan_p3(const __half* __restrict__ p,
                        const __half* __restrict__ gate,
                        const __half* __restrict__ xn,
                        const float* __restrict__ hin,
                        __half* __restrict__ mixed, int L, int CL) {
    int chain = blockIdx.x;
    int chunk = blockIdx.y;
    int b = chain / Hh;
    int h = chain % Hh;
    int s = threadIdx.x;

    float hst = hin[((size_t)chain * NC + chunk) * DSs + s];

    const size_t pstr = (size_t)Hh * 3 * DSs;
    size_t l0 = (size_t)chunk * CL;
    const __half* pb = p + ((size_t)b * L + l0) * pstr + (size_t)h * 3 * DSs + s;
    size_t goff = ((size_t)b * L + l0) * Dm + (size_t)h * DSs + s;
    const __half* gb = gate + goff;
    const __half* xb = xn + goff;
    __half* mb = mixed + goff;

    for (int l = 0; l < CL; l += 4) {
        float dv[4], bv[4], cv[4], gv[4], xv[4];
        #pragma unroll
        for (int u = 0; u < 4; u++) {
            const __half* pp = pb + (size_t)(l + u) * pstr;
            dv[u] = __half2float(__ldg(pp));
            bv[u] = __half2float(__ldg(pp + DSs));
            cv[u] = __half2float(__ldg(pp + 2 * DSs));
            gv[u] = __half2float(__ldg(gb + (size_t)(l + u) * Dm));
            xv[u] = __half2float(__ldg(xb + (size_t)(l + u) * Dm));
        }
        #pragma unroll
        for (int u = 0; u < 4; u++) {
            float dsg = sigmoidf_(dv[u]);
            hst = fmaf(dsg, hst, bv[u]);
            float ssm = cv[u] * hst;
            mb[(size_t)(l + u) * Dm] = __float2half_rn(fmaf(gv[u], ssm - xv[u], xv[u]));
        }
    }
}

// ---------------------------------------------------------------------------
// Launch
// ---------------------------------------------------------------------------
extern "C" void kernel_launch(void* const* d_in, const int* in_sizes, int n_in,
                              void* d_out, int out_size) {
    const float* x      = (const float*)d_in[0];
    const float* state  = (const float*)d_in[1];
    const float* norm_w = (const float*)d_in[2];
    const float* conv_w = (const float*)d_in[3];
    const float* conv_b = (const float*)d_in[4];
    const float* pp_w   = (const float*)d_in[5];
    const float* pp_b   = (const float*)d_in[6];
    const float* gp_w   = (const float*)d_in[7];
    const float* gp_b   = (const float*)d_in[8];
    const float* op_w   = (const float*)d_in[9];
    const float* op_b   = (const float*)d_in[10];
    float* out = (float*)d_out;

    int BL = in_sizes[0] / Dm;                 // 8192
    int Bb = in_sizes[1] / (Hh * DSs);         // 2
    int L  = BL / Bb;                          // 4096
    int NBc = Bb * Hh;                         // 64
    int CL  = L / NC;                          // 64

    float* scratch;
    cudaGetSymbolAddress((void**)&scratch, g_scratch);
    __half* xnH   = (__half*)(scratch + OFF_XNH);
    __half* xcH   = (__half*)(scratch + OFF_XCH);
    __half* mxH   = (__half*)(scratch + OFF_MXH);
    __half* pH    = (__half*)(scratch + OFF_PH);
    __half* gateH = (__half*)(scratch + OFF_GATEH);
    float*  scanA = scratch + OFF_SCANA;
    float*  scanH = scratch + OFF_SCANH;
    float*  scanI = scratch + OFF_SCANI;
    __half* ppH   = (__half*)(scratch + OFF_PPH);
    __half* gpH   = (__half*)(scratch + OFF_GPH);
    __half* opH   = (__half*)(scratch + OFF_OPH);

    // 0) Weight transposes + fp16 round (single fused launch)
    transpose_half_all<<<dim3(P_COLS / 32, Dm / 32, 3), dim3(32, 8)>>>(
        pp_w, gp_w, op_w, ppH, gpH, opH);

    // 1) RMSNorm (fp16 xn)
    rmsnorm_kernel<<<BL, 256>>>(x, norm_w, xnH);

    // 2) Causal conv + SiLU (fp16 xc)
    conv_silu_kernel<<<dim3(Dm / 128, L / 256, Bb), 128>>>(xnH, conv_w, conv_b, xcH, L);

    // 3) p = xn @ pp_w + pp_b (fp16 out)
    gemm_fp16<0><<<dim3(P_COLS / 128, BL / 128), 256>>>(
        xnH, ppH, pp_b, nullptr, pH, BL, P_COLS, Dm);

    // 4) gate = sigmoid(xc @ gp_w + gp_b) (fp16 out)
    gemm_fp16<1><<<dim3(Dm / 128, BL / 128), 256>>>(
        xcH, gpH, gp_b, nullptr, gateH, BL, Dm, Dm);

    // 5) scan (3 passes); h_last to tail of output
    scan_p1<<<dim3(NBc, NC), DSs>>>(pH, scanA, scanH, L, CL);
    scan_mid<<<NBc, DSs>>>(scanA, scanH, state, scanI, out + (size_t)BL * Dm);
    scan_p3<<<dim3(NBc, NC), DSs>>>(pH, gateH, xnH, scanI, mxH, L, CL);

    // 6) y = mixed @ op_w + op_b + x (fp32 out)
    gemm_fp16<2><<<dim3(Dm / 128, BL / 128), 256>>>(
        mxH, opH, op_b, x, out, BL, Dm, Dm);
}

// round 12
// speedup vs baseline: 1.7279x; 1.2077x over previous
#include <cuda_runtime.h>
#include <cuda_fp16.h>
#include <cstdint>
#include <cstddef>
#include <math.h>

// Problem constants
#define Dm   2048
#define Hh   32
#define DSs  64
#define KK   4
#define EPSf 1e-6f
#define NC   64            // scan chunks

// Max sizes (B=2, L=4096)
#define BL_MAX  8192
#define P_COLS  (3*Dm)   // 6144
#define NB_MAX  64       // B*H chains

// Scratch layout (in floats)
#define OFF_XNH    ((size_t)0)                               // half[BL*Dm]
#define OFF_XCH    (OFF_XNH + (size_t)BL_MAX*Dm/2)
#define OFF_MXH    (OFF_XCH + (size_t)BL_MAX*Dm/2)
#define OFF_PH     (OFF_MXH + (size_t)BL_MAX*Dm/2)           // half[BL*P_COLS]
#define OFF_GATEH  (OFF_PH  + (size_t)BL_MAX*P_COLS/2)       // half[BL*Dm]
#define OFF_SCANA  (OFF_GATEH + (size_t)BL_MAX*Dm/2)
#define OFF_SCANH  (OFF_SCANA + (size_t)NB_MAX*NC*DSs)
#define OFF_SCANI  (OFF_SCANH + (size_t)NB_MAX*NC*DSs)
#define OFF_PPH    (OFF_SCANI + (size_t)NB_MAX*NC*DSs)       // half[P_COLS*Dm]
#define OFF_GPH    (OFF_PPH + (size_t)P_COLS*Dm/2)
#define OFF_OPH    (OFF_GPH + (size_t)Dm*Dm/2)
#define SCRATCH_FLOATS (OFF_OPH + (size_t)Dm*Dm/2)

__device__ float g_scratch[SCRATCH_FLOATS];

// ---------------------------------------------------------------------------
// Helpers
// ---------------------------------------------------------------------------
__device__ __forceinline__ void mma_f16(float* c, const uint32_t* a, const uint32_t* b) {
    asm volatile(
        "mma.sync.aligned.m16n8k16.row.col.f32.f16.f16.f32 "
        "{%0,%1,%2,%3}, {%4,%5,%6,%7}, {%8,%9}, {%0,%1,%2,%3};\n"
        : "+f"(c[0]), "+f"(c[1]), "+f"(c[2]), "+f"(c[3])
        : "r"(a[0]), "r"(a[1]), "r"(a[2]), "r"(a[3]),
          "r"(b[0]), "r"(b[1]));
}

__device__ __forceinline__ void ldsm_x4(uint32_t* r, uint32_t addr) {
    asm volatile("ldmatrix.sync.aligned.m8n8.x4.shared.b16 {%0,%1,%2,%3}, [%4];"
        : "=r"(r[0]), "=r"(r[1]), "=r"(r[2]), "=r"(r[3]) : "r"(addr));
}

__device__ __forceinline__ void ldsm_x2(uint32_t* r, uint32_t addr) {
    asm volatile("ldmatrix.sync.aligned.m8n8.x2.shared.b16 {%0,%1}, [%2];"
        : "=r"(r[0]), "=r"(r[1]) : "r"(addr));
}

__device__ __forceinline__ void cp_async16(void* smem, const void* gmem) {
    uint32_t s = (uint32_t)__cvta_generic_to_shared(smem);
    asm volatile("cp.async.cg.shared.global [%0], [%1], 16;\n" :: "r"(s), "l"(gmem));
}

__device__ __forceinline__ float sigmoidf_(float v) {
    return 1.0f / (1.0f + __expf(-v));
}

__device__ __forceinline__ uint2 pack4h(float a, float b, float c, float d) {
    __half2 lo = __floats2half2_rn(a, b);
    __half2 hi = __floats2half2_rn(c, d);
    uint2 r;
    r.x = *(uint32_t*)&lo;
    r.y = *(uint32_t*)&hi;
    return r;
}

// ---------------------------------------------------------------------------
// Fused weight transpose + fp16 round for all three weights (z-indexed).
// ---------------------------------------------------------------------------
__global__ void transpose_half_all(const float* __restrict__ pp,
                                   const float* __restrict__ gp,
                                   const float* __restrict__ op,
                                   __half* __restrict__ ppT,
                                   __half* __restrict__ gpT,
                                   __half* __restrict__ opT) {
    const float* W;
    __half* WT;
    int N;
    if (blockIdx.z == 0)      { W = pp; WT = ppT; N = P_COLS; }
    else if (blockIdx.z == 1) { W = gp; WT = gpT; N = Dm; }
    else                      { W = op; WT = opT; N = Dm; }
    if (blockIdx.x * 32 >= N) return;

    __shared__ float t[32][33];
    int n0 = blockIdx.x * 32, k0 = blockIdx.y * 32;
    int tx = threadIdx.x, ty = threadIdx.y;
    #pragma unroll
    for (int i = 0; i < 4; i++)
        t[ty + 8*i][tx] = W[(size_t)(k0 + ty + 8*i) * N + n0 + tx];
    __syncthreads();
    int tid = ty * 32 + tx;
    int n_l = tid >> 3;
    int kq  = tid & 7;
    float a = t[kq*4 + 0][n_l];
    float b = t[kq*4 + 1][n_l];
    float c = t[kq*4 + 2][n_l];
    float d = t[kq*4 + 3][n_l];
    *(uint2*)&WT[(size_t)(n0 + n_l) * Dm + k0 + kq*4] = pack4h(a, b, c, d);
}

// ---------------------------------------------------------------------------
// RMSNorm (stores fp16 xn)
// ---------------------------------------------------------------------------
__global__ void rmsnorm_kernel(const float* __restrict__ x,
                               const float* __restrict__ w,
                               __half* __restrict__ xn) {
    size_t row = blockIdx.x;
    const float4* xr = (const float4*)(x + row * Dm);
    float4 v0 = xr[threadIdx.x];
    float4 v1 = xr[threadIdx.x + 256];
    float ss = v0.x*v0.x + v0.y*v0.y + v0.z*v0.z + v0.w*v0.w
             + v1.x*v1.x + v1.y*v1.y + v1.z*v1.z + v1.w*v1.w;
    #pragma unroll
    for (int o = 16; o > 0; o >>= 1) ss += __shfl_xor_sync(0xffffffffu, ss, o);
    __shared__ float red[8];
    if ((threadIdx.x & 31) == 0) red[threadIdx.x >> 5] = ss;
    __syncthreads();
    float tot = red[0] + red[1] + red[2] + red[3] + red[4] + red[5] + red[6] + red[7];
    float inv = rsqrtf(tot * (1.0f / Dm) + EPSf);

    const float4* wr = (const float4*)w;
    float4 w0 = wr[threadIdx.x];
    float4 w1 = wr[threadIdx.x + 256];
    uint2* orow = (uint2*)(xn + row * Dm);
    orow[threadIdx.x] = pack4h(v0.x * w0.x * inv, v0.y * w0.y * inv,
                               v0.z * w0.z * inv, v0.w * w0.w * inv);
    orow[threadIdx.x + 256] = pack4h(v1.x * w1.x * inv, v1.y * w1.y * inv,
                                     v1.z * w1.z * inv, v1.w * w1.w * inv);
}

// ---------------------------------------------------------------------------
// Causal depthwise conv (K=4) + SiLU (fp16 in, fp16 out; fp32 math)
// ---------------------------------------------------------------------------
__global__ void conv_silu_kernel(const __half* __restrict__ xn,
                                 const float* __restrict__ cw,
                                 const float* __restrict__ cb,
                                 __half* __restrict__ xc, int L) {
    int d  = blockIdx.x * 128 + threadIdx.x;
    int b  = blockIdx.z;
    int l0 = blockIdx.y * 256;
    float w0 = cw[d*KK + 0], w1 = cw[d*KK + 1], w2 = cw[d*KK + 2], w3 = cw[d*KK + 3];
    float bb = cb[d];
    const __half* base = xn + ((size_t)b * L) * Dm + d;
    __half* obase      = xc + ((size_t)b * L) * Dm + d;

    float xm3 = (l0 >= 3) ? __half2float(base[(size_t)(l0 - 3) * Dm]) : 0.0f;
    float xm2 = (l0 >= 2) ? __half2float(base[(size_t)(l0 - 2) * Dm]) : 0.0f;
    float xm1 = (l0 >= 1) ? __half2float(base[(size_t)(l0 - 1) * Dm]) : 0.0f;

    #pragma unroll 8
    for (int l = l0; l < l0 + 256; l++) {
        float xcur = __half2float(base[(size_t)l * Dm]);
        float acc = bb + w0 * xm3 + w1 * xm2 + w2 * xm1 + w3 * xcur;
        float sv = acc * sigmoidf_(acc);
        obase[(size_t)l * Dm] = __float2half_rn(sv);
        xm3 = xm2; xm2 = xm1; xm1 = xcur;
    }
}

// ---------------------------------------------------------------------------
// FP16 GEMM (fp32 accum), BK=64, ldmatrix, double-buffered dynamic smem.
//   MODE 0: +bias -> half out (p)
//   MODE 1: sigmoid(+bias) -> half out (gate)
//   MODE 2: +bias+res -> float out (y)
// Tiles: BM=128, BN=128, BK=64, m16n8k16, 256 threads (8 warps of 64x32).
// ---------------------------------------------------------------------------
#define FSTR 72                   // halves per SMEM row (72 mod 32 = 8)
#define TILE_H (128 * FSTR)       // 9216 halves per tile matrix
#define GEMM_SMEM_BYTES (4 * TILE_H * 2)   // 73728 B

template<int MODE>
__global__ __launch_bounds__(256, 2)
void gemm_fp16(const __half* __restrict__ A, const __half* __restrict__ BT,
               const float* __restrict__ bias, const float* __restrict__ res,
               void* __restrict__ Cout, int M, int N, int K) {
    extern __shared__ __half smh[];
    // layout: A0 | A1 | B0 | B1, each TILE_H halves

    int tid  = threadIdx.x;
    int wid  = tid >> 5;
    int lane = tid & 31;
    int wm = (wid & 1) * 64;
    int wn = (wid >> 1) * 32;
    int g = lane >> 2;
    int t = lane & 3;

    int bm = blockIdx.y * 128;
    int bn = blockIdx.x * 128;

    const __half* Aptr = A  + (size_t)bm * K;
    const __half* Bptr = BT + (size_t)bn * K;

    float acc[4][4][4];
    #pragma unroll
    for (int i = 0; i < 4; i++)
        #pragma unroll
        for (int j = 0; j < 4; j++)
            #pragma unroll
            for (int q = 0; q < 4; q++) acc[i][j][q] = 0.0f;

    // Loader: 1024 16B-chunks per matrix tile, 4 per thread.
    // chunk id = tid + i*256 -> row = id>>3, colchunk = id&7 (8 halves each)
    int l_r = tid >> 3;            // 0..31
    int l_c = (tid & 7) * 8;       // 0..56

    uint32_t smBase = (uint32_t)__cvta_generic_to_shared(&smh[0]);
    uint32_t a_off = (uint32_t)(((wm + (lane & 15)) * FSTR + ((lane >> 4) << 3)) * 2);
    uint32_t b_off = (uint32_t)(((wn + (lane & 7)) * FSTR + (((lane >> 3) & 1) << 3)) * 2);

    int NK = K / 64;

    // Prologue: stage 0
    {
        #pragma unroll
        for (int i = 0; i < 4; i++) {
            int r = l_r + 32 * i;
            cp_async16(&smh[r * FSTR + l_c],            Aptr + (size_t)r * K + l_c);
            cp_async16(&smh[2 * TILE_H + r * FSTR + l_c], Bptr + (size_t)r * K + l_c);
        }
        asm volatile("cp.async.commit_group;\n" ::);
    }

    for (int kt = 0; kt < NK; kt++) {
        int buf = kt & 1;
        if (kt + 1 < NK) {
            int k0 = (kt + 1) * 64;
            __half* nA = smh + (buf ^ 1) * TILE_H;
            __half* nB = smh + (2 + (buf ^ 1)) * TILE_H;
            #pragma unroll
            for (int i = 0; i < 4; i++) {
                int r = l_r + 32 * i;
                cp_async16(&nA[r * FSTR + l_c], Aptr + (size_t)r * K + k0 + l_c);
                cp_async16(&nB[r * FSTR + l_c], Bptr + (size_t)r * K + k0 + l_c);
            }
            asm volatile("cp.async.commit_group;\n" ::);
            asm volatile("cp.async.wait_group 1;\n" ::);
        } else {
            asm volatile("cp.async.wait_group 0;\n" ::);
        }
        __syncthreads();

        uint32_t aBase = smBase + (uint32_t)(buf * TILE_H * 2) + a_off;
        uint32_t bBase = smBase + (uint32_t)((2 + buf) * TILE_H * 2) + b_off;

        #pragma unroll
        for (int k16 = 0; k16 < 4; k16++) {
            uint32_t af[4][4], bf[4][2];
            #pragma unroll
            for (int mt = 0; mt < 4; mt++)
                ldsm_x4(af[mt], aBase + (uint32_t)(mt * 16 * FSTR * 2 + k16 * 32));
            #pragma unroll
            for (int nt = 0; nt < 4; nt++)
                ldsm_x2(bf[nt], bBase + (uint32_t)(nt * 8 * FSTR * 2 + k16 * 32));
            #pragma unroll
            for (int mt = 0; mt < 4; mt++)
                #pragma unroll
                for (int nt = 0; nt < 4; nt++)
                    mma_f16(acc[mt][nt], af[mt], bf[nt]);
        }
        __syncthreads();
    }

    // Epilogue
    #pragma unroll
    for (int mt = 0; mt < 4; mt++) {
        #pragma unroll
        for (int nt = 0; nt < 4; nt++) {
            int r = bm + wm + mt * 16 + g;
            int c = bn + wn + nt * 8 + 2 * t;
            float b0 = bias[c], b1 = bias[c + 1];
            float v00 = acc[mt][nt][0] + b0;
            float v01 = acc[mt][nt][1] + b1;
            float v10 = acc[mt][nt][2] + b0;
            float v11 = acc[mt][nt][3] + b1;
            if (MODE == 1) {
                v00 = sigmoidf_(v00); v01 = sigmoidf_(v01);
                v10 = sigmoidf_(v10); v11 = sigmoidf_(v11);
            }
            if (MODE == 2) {
                float* C = (float*)Cout;
                float2 r0 = *(const float2*)&res[(size_t)r * N + c];
                float2 r1 = *(const float2*)&res[(size_t)(r + 8) * N + c];
                v00 += r0.x; v01 += r0.y; v10 += r1.x; v11 += r1.y;
                *(float2*)&C[(size_t)r * N + c]       = make_float2(v00, v01);
                *(float2*)&C[(size_t)(r + 8) * N + c] = make_float2(v10, v11);
            } else {
                __half* C = (__half*)Cout;
                *(__half2*)&C[(size_t)r * N + c]       = __floats2half2_rn(v00, v01);
                *(__half2*)&C[(size_t)(r + 8) * N + c] = __floats2half2_rn(v10, v11);
            }
        }
    }
}

// ---------------------------------------------------------------------------
// Chunked parallel scan (3 passes). p half, gate half, xn half, mixed half.
// ---------------------------------------------------------------------------
__global__ void scan_p1(const __half* __restrict__ p,
                        float* __restrict__ Ac, float* __restrict__ Hc,
                        int L, int CL) {
    int chain = blockIdx.x;
    int chunk = blockIdx.y;
    int b = chain / Hh;
    int h = chain % Hh;
    int s = threadIdx.x;

    const size_t pstr = (size_t)Hh * 3 * DSs;
    const __half* pb = p + ((size_t)b * L + (size_t)chunk * CL) * pstr
                         + (size_t)h * 3 * DSs + s;

    float A = 1.0f, hl = 0.0f;
    for (int l = 0; l < CL; l += 4) {
        float d0 = __half2float(__ldg(pb + (size_t)(l+0) * pstr));
        float d1 = __half2float(__ldg(pb + (size_t)(l+1) * pstr));
        float d2 = __half2float(__ldg(pb + (size_t)(l+2) * pstr));
        float d3 = __half2float(__ldg(pb + (size_t)(l+3) * pstr));
        float b0 = __half2float(__ldg(pb + (size_t)(l+0) * pstr + DSs));
        float b1 = __half2float(__ldg(pb + (size_t)(l+1) * pstr + DSs));
        float b2 = __half2float(__ldg(pb + (size_t)(l+2) * pstr + DSs));
        float b3 = __half2float(__ldg(pb + (size_t)(l+3) * pstr + DSs));
        float s0 = sigmoidf_(d0), s1 = sigmoidf_(d1);
        float s2 = sigmoidf_(d2), s3 = sigmoidf_(d3);
        A *= s0; hl = fmaf(s0, hl, b0);
        A *= s1; hl = fmaf(s1, hl, b1);
        A *= s2; hl = fmaf(s2, hl, b2);
        A *= s3; hl = fmaf(s3, hl, b3);
    }
    size_t idx = ((size_t)chain * NC + chunk) * DSs + s;
    Ac[idx] = A;
    Hc[idx] = hl;
}

__global__ void scan_mid(const float* __restrict__ Ac, const float* __restrict__ Hc,
                         const float* __restrict__ st0,
                         float* __restrict__ hin, float* __restrict__ hlast) {
    int chain = blockIdx.x;
    int s = threadIdx.x;
    float h = st0[(size_t)chain * DSs + s];
    #pragma unroll
    for (int c = 0; c < NC; c++) {
        size_t idx = ((size_t)chain * NC + c) * DSs + s;
        hin[idx] = h;
        h = fmaf(Ac[idx], h, Hc[idx]);
    }
    hlast[(size_t)chain * DSs + s] = h;
}

__global__ void scan_p3(const __half* __restrict__ p,
                        const __half* __restrict__ gate,
                        const __half* __restrict__ xn,
                        const float* __restrict__ hin,
                        __half* __restrict__ mixed, int L, int CL) {
    int chain = blockIdx.x;
    int chunk = blockIdx.y;
    int b = chain / Hh;
    int h = chain % Hh;
    int s = threadIdx.x;

    float hst = hin[((size_t)chain * NC + chunk) * DSs + s];

    const size_t pstr = (size_t)Hh * 3 * DSs;
    size_t l0 = (size_t)chunk * CL;
    const __half* pb = p + ((size_t)b * L + l0) * pstr + (size_t)h * 3 * DSs + s;
    size_t goff = ((size_t)b * L + l0) * Dm + (size_t)h * DSs + s;
    const __half* gb = gate + goff;
    const __half* xb = xn + goff;
    __half* mb = mixed + goff;

    for (int l = 0; l < CL; l += 4) {
        float dv[4], bv[4], cv[4], gv[4], xv[4];
        #pragma unroll
        for (int u = 0; u < 4; u++) {
            const __half* pp = pb + (size_t)(l + u) * pstr;
            dv[u] = __half2float(__ldg(pp));
            bv[u] = __half2float(__ldg(pp + DSs));
            cv[u] = __half2float(__ldg(pp + 2 * DSs));
            gv[u] = __half2float(__ldg(gb + (size_t)(l + u) * Dm));
            xv[u] = __half2float(__ldg(xb + (size_t)(l + u) * Dm));
        }
        #pragma unroll
        for (int u = 0; u < 4; u++) {
            float dsg = sigmoidf_(dv[u]);
            hst = fmaf(dsg, hst, bv[u]);
            float ssm = cv[u] * hst;
            mb[(size_t)(l + u) * Dm] = __float2half_rn(fmaf(gv[u], ssm - xv[u], xv[u]));
        }
    }
}

// ---------------------------------------------------------------------------
// Launch
// ---------------------------------------------------------------------------
extern "C" void kernel_launch(void* const* d_in, const int* in_sizes, int n_in,
                              void* d_out, int out_size) {
    const float* x      = (const float*)d_in[0];
    const float* state  = (const float*)d_in[1];
    const float* norm_w = (const float*)d_in[2];
    const float* conv_w = (const float*)d_in[3];
    const float* conv_b = (const float*)d_in[4];
    const float* pp_w   = (const float*)d_in[5];
    const float* pp_b   = (const float*)d_in[6];
    const float* gp_w   = (const float*)d_in[7];
    const float* gp_b   = (const float*)d_in[8];
    const float* op_w   = (const float*)d_in[9];
    const float* op_b   = (const float*)d_in[10];
    float* out = (float*)d_out;

    int BL = in_sizes[0] / Dm;                 // 8192
    int Bb = in_sizes[1] / (Hh * DSs);         // 2
    int L  = BL / Bb;                          // 4096
    int NBc = Bb * Hh;                         // 64
    int CL  = L / NC;                          // 64

    static bool attr_done = false;
    if (!attr_done) {
        cudaFuncSetAttribute(gemm_fp16<0>, cudaFuncAttributeMaxDynamicSharedMemorySize, GEMM_SMEM_BYTES);
        cudaFuncSetAttribute(gemm_fp16<1>, cudaFuncAttributeMaxDynamicSharedMemorySize, GEMM_SMEM_BYTES);
        cudaFuncSetAttribute(gemm_fp16<2>, cudaFuncAttributeMaxDynamicSharedMemorySize, GEMM_SMEM_BYTES);
        attr_done = true;
    }

    float* scratch;
    cudaGetSymbolAddress((void**)&scratch, g_scratch);
    __half* xnH   = (__half*)(scratch + OFF_XNH);
    __half* xcH   = (__half*)(scratch + OFF_XCH);
    __half* mxH   = (__half*)(scratch + OFF_MXH);
    __half* pH    = (__half*)(scratch + OFF_PH);
    __half* gateH = (__half*)(scratch + OFF_GATEH);
    float*  scanA = scratch + OFF_SCANA;
    float*  scanH = scratch + OFF_SCANH;
    float*  scanI = scratch + OFF_SCANI;
    __half* ppH   = (__half*)(scratch + OFF_PPH);
    __half* gpH   = (__half*)(scratch + OFF_GPH);
    __half* opH   = (__half*)(scratch + OFF_OPH);

    // 0) Weight transposes + fp16 round (single fused launch)
    transpose_half_all<<<dim3(P_COLS / 32, Dm / 32, 3), dim3(32, 8)>>>(
        pp_w, gp_w, op_w, ppH, gpH, opH);

    // 1) RMSNorm (fp16 xn)
    rmsnorm_kernel<<<BL, 256>>>(x, norm_w, xnH);

    // 2) Causal conv + SiLU (fp16 xc)
    conv_silu_kernel<<<dim3(Dm / 128, L / 256, Bb), 128>>>(xnH, conv_w, conv_b, xcH, L);

    // 3) p = xn @ pp_w + pp_b (fp16 out)
    gemm_fp16<0><<<dim3(P_COLS / 128, BL / 128), 256, GEMM_SMEM_BYTES>>>(
        xnH, ppH, pp_b, nullptr, pH, BL, P_COLS, Dm);

    // 4) gate = sigmoid(xc @ gp_w + gp_b) (fp16 out)
    gemm_fp16<1><<<dim3(Dm / 128, BL / 128), 256, GEMM_SMEM_BYTES>>>(
        xcH, gpH, gp_b, nullptr, gateH, BL, Dm, Dm);

    // 5) scan (3 passes); h_last to tail of output
    scan_p1<<<dim3(NBc, NC), DSs>>>(pH, scanA, scanH, L, CL);
    scan_mid<<<NBc, DSs>>>(scanA, scanH, state, scanI, out + (size_t)BL * Dm);
    scan_p3<<<dim3(NBc, NC), DSs>>>(pH, gateH, xnH, scanI, mxH, L, CL);

    // 6) y = mixed @ op_w + op_b + x (fp32 out)
    gemm_fp16<2><<<dim3(Dm / 128, BL / 128), 256, GEMM_SMEM_BYTES>>>(
        mxH, opH, op_b, x, out, BL, Dm, Dm);
}